// round 6
// baseline (speedup 1.0000x reference)
#include <cuda_runtime.h>
#include <stdint.h>

#define NB 8
#define NA 200000
#define NG 64
#define NK 4
#define NCHUNK 16
#define CHUNK 12500
#define GQ 4
#define MAXPOS 128

// ---------------- scratch (static __device__, no allocation) ----------------
__device__ unsigned long long g_part[NB * NG * NCHUNK * NK];  // chunk-partial top4 keys
__device__ float g_topval[NB][NG][NK];
__device__ int   g_topidx[NB][NG][NK];
__device__ unsigned long long g_poskeys[NB][NA];
__device__ int g_npos[NB];
__device__ int g_counts[NB][NG];

struct SplitKeys { unsigned int k[2 * NB]; };

// ---------------- threefry2x32 (exact JAX kernel: 20 rounds) ----------------
__host__ __device__ inline void threefry2x32(unsigned int k0, unsigned int k1,
                                             unsigned int c0, unsigned int c1,
                                             unsigned int &o0, unsigned int &o1) {
  unsigned int ks2 = 0x1BD11BDAu ^ k0 ^ k1;
  unsigned int x0 = c0 + k0, x1 = c1 + k1;
#define TFR(r) do { x0 += x1; x1 = (x1 << (r)) | (x1 >> (32 - (r))); x1 ^= x0; } while (0)
  TFR(13); TFR(15); TFR(26); TFR(6);
  x0 += k1;  x1 += ks2 + 1u;
  TFR(17); TFR(29); TFR(16); TFR(24);
  x0 += ks2; x1 += k0 + 2u;
  TFR(13); TFR(15); TFR(26); TFR(6);
  x0 += k0;  x1 += k1 + 3u;
  TFR(17); TFR(29); TFR(16); TFR(24);
  x0 += k1;  x1 += ks2 + 4u;
  TFR(13); TFR(15); TFR(26); TFR(6);
  x0 += ks2; x1 += k0 + 5u;
#undef TFR
  o0 = x0; o1 = x1;
}

// one ulp below a non-negative float (0 stays 0 -> filter disabled)
__device__ __forceinline__ float prev_ulp(float v) {
  unsigned int b = __float_as_uint(v);
  return __uint_as_float(b ? b - 1u : 0u);
}

// insert key into descending sorted 4-list; caller guarantees key > t[3]
__device__ __forceinline__ void insert4(unsigned long long *t, unsigned long long key) {
  if (key > t[1]) {
    t[3] = t[2]; t[2] = t[1];
    if (key > t[0]) { t[1] = t[0]; t[0] = key; } else { t[1] = key; }
  } else {
    if (key > t[2]) { t[3] = t[2]; t[2] = key; } else { t[3] = key; }
  }
}

// merge two descending sorted 4-lists -> top4 into a
__device__ __forceinline__ void merge4(unsigned long long *a, const unsigned long long *b) {
  unsigned long long out[4];
  int i = 0, j = 0;
#pragma unroll
  for (int k = 0; k < 4; k++) {
    unsigned long long av = a[i], bv = b[j];
    if (av >= bv) { out[k] = av; i++; } else { out[k] = bv; j++; }
  }
#pragma unroll
  for (int k = 0; k < 4; k++) a[k] = out[k];
}

__global__ void init_kernel() {
  if (threadIdx.x < NB) g_npos[threadIdx.x] = 0;
}

// ---------------- phase 1: per-GT top-4 over anchors (GT-major) -------------
// grid: x = anchor chunk (16), y = gt group (16 groups of 4), z = image (8)
__global__ void __launch_bounds__(256) phase1_kernel(const float *__restrict__ anchors,
                                                     const float *__restrict__ gt) {
  const int b = blockIdx.z;
  const int g0 = blockIdx.y * GQ;
  const int ch = blockIdx.x;
  const int tid = threadIdx.x;

  __shared__ float sg[GQ][5];
  if (tid < GQ) {
    const float *gp = gt + (size_t)(b * NG + g0 + tid) * 4;
    float cx = gp[0], cy = gp[1], w = gp[2], h = gp[3];
    float tx = __fmul_rn(0.5f, w), ty = __fmul_rn(0.5f, h);
    float x1 = __fsub_rn(cx, tx), x2 = __fadd_rn(cx, tx);
    float y1 = __fsub_rn(cy, ty), y2 = __fadd_rn(cy, ty);
    sg[tid][0] = x1; sg[tid][1] = y1; sg[tid][2] = x2; sg[tid][3] = y2;
    sg[tid][4] = __fmul_rn(__fsub_rn(x2, x1), __fsub_rn(y2, y1));
  }
  __syncthreads();

  float gx1[GQ], gy1[GQ], gx2[GQ], gy2[GQ], ga[GQ];
#pragma unroll
  for (int j = 0; j < GQ; j++) {
    gx1[j] = sg[j][0]; gy1[j] = sg[j][1]; gx2[j] = sg[j][2]; gy2[j] = sg[j][3]; ga[j] = sg[j][4];
  }

  unsigned long long top[GQ][4];
  float min4safe[GQ];  // one ulp below value of top[j][3]; 0 => filter off
#pragma unroll
  for (int j = 0; j < GQ; j++) {
    min4safe[j] = 0.0f;
#pragma unroll
    for (int k = 0; k < 4; k++) top[j][k] = 0ull;
  }

  const int a0 = ch * CHUNK;
  const float4 *ap = reinterpret_cast<const float4 *>(anchors) + (size_t)b * NA;
  for (int a = a0 + tid; a < a0 + CHUNK; a += 256) {
    float4 v = ap[a];
    float tx = __fmul_rn(0.5f, v.z), ty = __fmul_rn(0.5f, v.w);
    float ax1 = __fsub_rn(v.x, tx), ax2 = __fadd_rn(v.x, tx);
    float ay1 = __fsub_rn(v.y, ty), ay2 = __fadd_rn(v.y, ty);
    float aa = __fmul_rn(__fsub_rn(ax2, ax1), __fsub_rn(ay2, ay1));
    unsigned int idxk = 0xFFFFFFFFu - (unsigned int)a;  // ties -> lower index wins
#pragma unroll
    for (int j = 0; j < GQ; j++) {
      float ltx = fmaxf(gx1[j], ax1);
      float lty = fmaxf(gy1[j], ay1);
      float rbx = fminf(gx2[j], ax2);
      float rby = fminf(gy2[j], ay2);
      float wx = fmaxf(__fsub_rn(rbx, ltx), 0.0f);
      float wy = fmaxf(__fsub_rn(rby, lty), 0.0f);
      float inter = __fmul_rn(wx, wy);
      if (inter == 0.0f) continue;  // iou = 0 can never enter top4 (keys init 0 dominate via idx only when empty; value 0 can't beat min4 once filled, and with min4safe=0 the div path handles warmup)
      float uni = __fsub_rn(__fadd_rn(ga[j], aa), inter);
      // rounding-safe reject: inter < rd(min4safe * uni)  =>  div_rn(inter,uni) < top4-min value
      if (inter < __fmul_rd(min4safe[j], uni)) continue;
      float iou = __fdiv_rn(inter, uni);
      unsigned long long key = ((unsigned long long)__float_as_uint(iou) << 32) | idxk;
      if (key > top[j][3]) {
        insert4(top[j], key);
        min4safe[j] = prev_ulp(__uint_as_float((unsigned int)(top[j][3] >> 32)));
      }
    }
  }

  __shared__ unsigned long long red[256 * 4];
  for (int j = 0; j < GQ; j++) {
#pragma unroll
    for (int k = 0; k < 4; k++) red[tid * 4 + k] = top[j][k];
    __syncthreads();
    for (int s = 128; s > 0; s >>= 1) {
      if (tid < s) merge4(&red[tid * 4], &red[(tid + s) * 4]);
      __syncthreads();
    }
    if (tid == 0) {
      size_t base = (size_t)((b * NG + g0 + j) * NCHUNK + ch) * 4;
#pragma unroll
      for (int k = 0; k < 4; k++) g_part[base + k] = red[k];
    }
    __syncthreads();
  }
}

// ---------------- phase 1b: merge chunk partials ----------------------------
__global__ void merge_parts_kernel() {
  int t = blockIdx.x * blockDim.x + threadIdx.x;
  if (t >= NB * NG) return;
  unsigned long long best[4] = {0ull, 0ull, 0ull, 0ull};
  for (int c = 0; c < NCHUNK; c++) {
    const unsigned long long *p = &g_part[(size_t)(t * NCHUNK + c) * 4];
#pragma unroll
    for (int k = 0; k < 4; k++) {
      unsigned long long key = p[k];
      if (key > best[3]) insert4(best, key);
    }
  }
  int b = t >> 6, g = t & 63;
#pragma unroll
  for (int k = 0; k < 4; k++) {
    g_topval[b][g][k] = __uint_as_float((unsigned int)(best[k] >> 32));
    g_topidx[b][g][k] = (int)(0xFFFFFFFFu - (unsigned int)best[k]);
  }
}

// ---------------- phase 2: anchor-major labeling + positive collection ------
// grid: x = anchor blocks (782), y = image (8)
__global__ void __launch_bounds__(256) phase2_kernel(const float *__restrict__ anchors,
                                                     const float *__restrict__ gt,
                                                     SplitKeys sk) {
  const int b = blockIdx.y;
  const int tid = threadIdx.x;
  __shared__ float4 sbox[NG];
  __shared__ float4 sah[NG];  // (area, hq, hq_safe, unused)
  if (tid < NG) {
    const float *gp = gt + (size_t)(b * NG + tid) * 4;
    float cx = gp[0], cy = gp[1], w = gp[2], h = gp[3];
    float tx = __fmul_rn(0.5f, w), ty = __fmul_rn(0.5f, h);
    float x1 = __fsub_rn(cx, tx), x2 = __fadd_rn(cx, tx);
    float y1 = __fsub_rn(cy, ty), y2 = __fadd_rn(cy, ty);
    sbox[tid] = make_float4(x1, y1, x2, y2);
    float hq = g_topval[b][tid][0];
    sah[tid] = make_float4(__fmul_rn(__fsub_rn(x2, x1), __fsub_rn(y2, y1)),
                           hq, prev_ulp(hq), 0.0f);
  }
  __syncthreads();
  int a = blockIdx.x * 256 + tid;
  if (a >= NA) return;  // NA % 32 == 0 -> warp-uniform exit, ballot below safe

  float4 v = reinterpret_cast<const float4 *>(anchors)[(size_t)b * NA + a];
  float tx = __fmul_rn(0.5f, v.z), ty = __fmul_rn(0.5f, v.w);
  float ax1 = __fsub_rn(v.x, tx), ax2 = __fadd_rn(v.x, tx);
  float ay1 = __fsub_rn(v.y, ty), ay2 = __fadd_rn(v.y, ty);
  float aa = __fmul_rn(__fsub_rn(ax2, ax1), __fsub_rn(ay2, ay1));

  float best = -1.0f;
  float bestsafe = 0.0f;  // one ulp below best (0 => filter off)
  int bg = 0;
  bool eq = false;
#pragma unroll 8
  for (int g = 0; g < NG; g++) {
    float4 gb = sbox[g];
    float4 ah = sah[g];
    float ltx = fmaxf(gb.x, ax1);
    float lty = fmaxf(gb.y, ay1);
    float rbx = fminf(gb.z, ax2);
    float rby = fminf(gb.w, ay2);
    float wx = fmaxf(__fsub_rn(rbx, ltx), 0.0f);
    float wy = fmaxf(__fsub_rn(rby, lty), 0.0f);
    float inter = __fmul_rn(wx, wy);
    if (inter == 0.0f) continue;  // iou 0: can't be >=0.7; eq only if hq==0 (impossible here); argmax slot irrelevant for non-positives
    float uni = __fsub_rn(__fadd_rn(ah.x, aa), inter);
    float msafe = fminf(bestsafe, ah.z);  // prev_ulp(min(best, hq_g)) since prev_ulp is monotone
    // rounding-safe reject: guarantees div < best AND div < hq_g (so != hq_g)
    if (inter < __fmul_rd(msafe, uni)) continue;
    float iou = __fdiv_rn(inter, uni);
    eq |= (iou == ah.y);                     // low-quality match (exact equality)
    if (iou > best) {                        // first-max == jnp.argmax
      best = iou; bg = g;
      bestsafe = __uint_as_float(__float_as_uint(iou) - 1u);  // iou > 0 here
    }
  }
  bool pos = (best >= 0.7f) || eq;

  // warp-aggregated append of subsample keys for positives
  unsigned int mask = __ballot_sync(0xFFFFFFFFu, pos);
  if (pos) {
    // JAX partitionable uniform bits for element a:
    //   (o0, o1) = threefry(key_b, (hi, lo) of 64-bit index) ; bits = o0 ^ o1
    unsigned int o0, o1;
    threefry2x32(sk.k[2 * b], sk.k[2 * b + 1], 0u, (unsigned int)a, o0, o1);
    unsigned int u = o0 ^ o1;
    float f = __uint_as_float((u >> 9) | 0x3f800000u);
    unsigned int rb = __float_as_uint(__fsub_rn(f, 1.0f));  // exact: f in [1,2)
    unsigned long long key =
        ((unsigned long long)rb << 32) | (unsigned int)(a * 64 + bg);
    int lane = tid & 31;
    int leader = __ffs(mask) - 1;
    int base = 0;
    if (lane == leader) base = atomicAdd(&g_npos[b], __popc(mask));
    base = __shfl_sync(mask, base, leader);
    int off = __popc(mask & ((1u << lane) - 1u));
    g_poskeys[b][base + off] = key;
  }
}

// ---------------- phase 3: select 128 smallest keys, count per GT -----------
__global__ void __launch_bounds__(1024) phase3_kernel() {
  const int b = blockIdx.x;
  const int tid = threadIdx.x;
  const int n = g_npos[b];
  __shared__ int hist[256];
  __shared__ unsigned long long s_prefix;
  __shared__ int s_want;

  unsigned long long thresh;
  if (n <= MAXPOS) {
    thresh = ~0ull;  // select all positives
  } else {
    if (tid == 0) { s_prefix = 0ull; s_want = MAXPOS; }
    __syncthreads();
    for (int shift = 56; shift >= 0; shift -= 8) {
      if (tid < 256) hist[tid] = 0;
      __syncthreads();
      unsigned long long pref = s_prefix;
      for (int i = tid; i < n; i += 1024) {
        unsigned long long k = g_poskeys[b][i];
        bool match = (shift == 56) ? true
                                   : ((k >> (shift + 8)) == (pref >> (shift + 8)));
        if (match) atomicAdd(&hist[(int)((k >> shift) & 255u)], 1);
      }
      __syncthreads();
      if (tid == 0) {
        int want = s_want;
        int d = 0;
        for (; d < 256; d++) {
          if (want <= hist[d]) break;
          want -= hist[d];
        }
        s_prefix = pref | ((unsigned long long)d << shift);
        s_want = want;
      }
      __syncthreads();
    }
    thresh = s_prefix;  // exact 128th-smallest key (keys unique)
  }

  __shared__ int cnt[NG];
  if (tid < NG) cnt[tid] = 0;
  __syncthreads();
  for (int i = tid; i < n; i += 1024) {
    unsigned long long k = g_poskeys[b][i];
    if (k <= thresh) atomicAdd(&cnt[(int)(k & 63u)], 1);
  }
  __syncthreads();
  if (tid < NG) g_counts[b][tid] = cnt[tid];
}

// ---------------- phase 4: emit [pr | gt | valid | scores] as float32 -------
__global__ void write_out_kernel(float *__restrict__ out) {
  int t = blockIdx.x * blockDim.x + threadIdx.x;
  if (t >= NB * NG * NK) return;
  int b = t >> 8;
  int g = (t >> 2) & 63;
  int k = t & 3;
  int c = g_counts[b][g];
  if (c > NK) c = NK;
  bool valid = k < c;
  float val = g_topval[b][g][k];
  int idx = g_topidx[b][g][k];
  const int SEC = NB * NG * NK;  // 2048
  int o = b * (NG * NK) + g * NK + k;
  out[o]           = valid ? (float)idx : -1.0f;
  out[SEC + o]     = valid ? (float)g : -1.0f;
  out[2 * SEC + o] = valid ? 1.0f : 0.0f;
  out[3 * SEC + o] = valid ? val : 0.0f;
}

// ---------------- launch -----------------------------------------------------
extern "C" void kernel_launch(void *const *d_in, const int *in_sizes, int n_in,
                              void *d_out, int out_size) {
  const float *anchors = (const float *)d_in[0];   // [8, 200000, 4] cxcywh
  const float *gt      = (const float *)d_in[1];   // [8, 64, 4] cxcywh

  // JAX partitionable split (foldlike): key_b = threefry((0,42), (0,b)), both words
  SplitKeys sk;
  for (int b = 0; b < NB; b++) {
    unsigned int o0, o1;
    threefry2x32(0u, 42u, 0u, (unsigned int)b, o0, o1);
    sk.k[2 * b] = o0;
    sk.k[2 * b + 1] = o1;
  }

  init_kernel<<<1, 32>>>();
  phase1_kernel<<<dim3(NCHUNK, NG / GQ, NB), 256>>>(anchors, gt);
  merge_parts_kernel<<<2, 256>>>();
  phase2_kernel<<<dim3((NA + 255) / 256, NB), 256>>>(anchors, gt, sk);
  phase3_kernel<<<NB, 1024>>>();
  write_out_kernel<<<NB, 256>>>((float *)d_out);
}

// round 7
// speedup vs baseline: 1.3670x; 1.3670x over previous
#include <cuda_runtime.h>
#include <stdint.h>

#define NB 8
#define NA 200000
#define NG 64
#define NK 4
#define NCHUNK 16
#define CHUNK 12500
#define GQ 4
#define MAXPOS 128
#define CAND_MAX 128

// ---------------- scratch (static __device__, no allocation) ----------------
__device__ float g_partf[NB * NG * NCHUNK * NK];  // chunk-partial top4 values
__device__ float g_topval[NB][NG][NK];            // global top4 values (sorted desc)
__device__ int   g_topidx[NB][NG][NK];            // recovered indices
__device__ unsigned long long g_cand[NB][NG][CAND_MAX];
__device__ int g_candcnt[NB][NG];
__device__ unsigned long long g_poskeys[NB][NA];
__device__ int g_npos[NB];
__device__ int g_counts[NB][NG];

struct SplitKeys { unsigned int k[2 * NB]; };

// ---------------- threefry2x32 (exact JAX kernel: 20 rounds) ----------------
__host__ __device__ inline void threefry2x32(unsigned int k0, unsigned int k1,
                                             unsigned int c0, unsigned int c1,
                                             unsigned int &o0, unsigned int &o1) {
  unsigned int ks2 = 0x1BD11BDAu ^ k0 ^ k1;
  unsigned int x0 = c0 + k0, x1 = c1 + k1;
#define TFR(r) do { x0 += x1; x1 = (x1 << (r)) | (x1 >> (32 - (r))); x1 ^= x0; } while (0)
  TFR(13); TFR(15); TFR(26); TFR(6);
  x0 += k1;  x1 += ks2 + 1u;
  TFR(17); TFR(29); TFR(16); TFR(24);
  x0 += ks2; x1 += k0 + 2u;
  TFR(13); TFR(15); TFR(26); TFR(6);
  x0 += k0;  x1 += k1 + 3u;
  TFR(17); TFR(29); TFR(16); TFR(24);
  x0 += k1;  x1 += ks2 + 4u;
  TFR(13); TFR(15); TFR(26); TFR(6);
  x0 += ks2; x1 += k0 + 5u;
#undef TFR
  o0 = x0; o1 = x1;
}

// insert u64 key into descending sorted 4-list; caller guarantees key > t[3]
__device__ __forceinline__ void insert4(unsigned long long *t, unsigned long long key) {
  if (key > t[1]) {
    t[3] = t[2]; t[2] = t[1];
    if (key > t[0]) { t[1] = t[0]; t[0] = key; } else { t[1] = key; }
  } else {
    if (key > t[2]) { t[3] = t[2]; t[2] = key; } else { t[3] = key; }
  }
}

// merge two descending sorted float 4-lists -> top4 into a
__device__ __forceinline__ void merge4f(float *a, const float *b) {
  float out[4];
  int i = 0, j = 0;
#pragma unroll
  for (int k = 0; k < 4; k++) {
    float av = a[i], bv = b[j];
    if (av >= bv) { out[k] = av; i++; } else { out[k] = bv; j++; }
  }
#pragma unroll
  for (int k = 0; k < 4; k++) a[k] = out[k];
}

__global__ void init_kernel() {
  int t = threadIdx.x + blockIdx.x * blockDim.x;
  if (t < NB) g_npos[t] = 0;
  if (t < NB * NG) ((int *)g_candcnt)[t] = 0;
}

// ---------------- phase 1: per-GT top-4 VALUES over anchors (GT-major) ------
// Branchless float tracking: no indices, no u64, no data-dependent branches.
// grid: x = anchor chunk (16), y = gt group (16 groups of 4), z = image (8)
__global__ void __launch_bounds__(256) phase1_kernel(const float *__restrict__ anchors,
                                                     const float *__restrict__ gt) {
  const int b = blockIdx.z;
  const int g0 = blockIdx.y * GQ;
  const int ch = blockIdx.x;
  const int tid = threadIdx.x;

  __shared__ float sg[GQ][5];
  if (tid < GQ) {
    const float *gp = gt + (size_t)(b * NG + g0 + tid) * 4;
    float cx = gp[0], cy = gp[1], w = gp[2], h = gp[3];
    float tx = __fmul_rn(0.5f, w), ty = __fmul_rn(0.5f, h);
    float x1 = __fsub_rn(cx, tx), x2 = __fadd_rn(cx, tx);
    float y1 = __fsub_rn(cy, ty), y2 = __fadd_rn(cy, ty);
    sg[tid][0] = x1; sg[tid][1] = y1; sg[tid][2] = x2; sg[tid][3] = y2;
    sg[tid][4] = __fmul_rn(__fsub_rn(x2, x1), __fsub_rn(y2, y1));
  }
  __syncthreads();

  float gx1[GQ], gy1[GQ], gx2[GQ], gy2[GQ], ga[GQ];
#pragma unroll
  for (int j = 0; j < GQ; j++) {
    gx1[j] = sg[j][0]; gy1[j] = sg[j][1]; gx2[j] = sg[j][2]; gy2[j] = sg[j][3]; ga[j] = sg[j][4];
  }

  float t0[GQ], t1[GQ], t2[GQ], t3[GQ];
#pragma unroll
  for (int j = 0; j < GQ; j++) { t0[j] = 0.0f; t1[j] = 0.0f; t2[j] = 0.0f; t3[j] = 0.0f; }

  const int a0 = ch * CHUNK;
  const float4 *ap = reinterpret_cast<const float4 *>(anchors) + (size_t)b * NA;
  for (int a = a0 + tid; a < a0 + CHUNK; a += 256) {
    float4 v = ap[a];
    float tx = __fmul_rn(0.5f, v.z), ty = __fmul_rn(0.5f, v.w);
    float ax1 = __fsub_rn(v.x, tx), ax2 = __fadd_rn(v.x, tx);
    float ay1 = __fsub_rn(v.y, ty), ay2 = __fadd_rn(v.y, ty);
    float aa = __fmul_rn(__fsub_rn(ax2, ax1), __fsub_rn(ay2, ay1));
#pragma unroll
    for (int j = 0; j < GQ; j++) {
      float ltx = fmaxf(gx1[j], ax1);
      float lty = fmaxf(gy1[j], ay1);
      float rbx = fminf(gx2[j], ax2);
      float rby = fminf(gy2[j], ay2);
      float wx = fmaxf(__fsub_rn(rbx, ltx), 0.0f);
      float wy = fmaxf(__fsub_rn(rby, lty), 0.0f);
      float inter = __fmul_rn(wx, wy);
      float uni = __fsub_rn(__fadd_rn(ga[j], aa), inter);
      float iou = __fdiv_rn(inter, uni);  // inter==0 -> +0/pos = +0, exact, no NaN
      // branchless sorted-desc top4 insert: 7 FMNMX
      float m0 = fmaxf(t0[j], iou), n0 = fminf(t0[j], iou);
      float m1 = fmaxf(t1[j], n0),  n1 = fminf(t1[j], n0);
      float m2 = fmaxf(t2[j], n1),  n2 = fminf(t2[j], n1);
      float m3 = fmaxf(t3[j], n2);
      t0[j] = m0; t1[j] = m1; t2[j] = m2; t3[j] = m3;
    }
  }

  __shared__ float red[256 * 4];
  for (int j = 0; j < GQ; j++) {
    red[tid * 4 + 0] = t0[j];
    red[tid * 4 + 1] = t1[j];
    red[tid * 4 + 2] = t2[j];
    red[tid * 4 + 3] = t3[j];
    __syncthreads();
    for (int s = 128; s > 0; s >>= 1) {
      if (tid < s) merge4f(&red[tid * 4], &red[(tid + s) * 4]);
      __syncthreads();
    }
    if (tid == 0) {
      size_t base = (size_t)((b * NG + g0 + j) * NCHUNK + ch) * 4;
#pragma unroll
      for (int k = 0; k < 4; k++) g_partf[base + k] = red[k];
    }
    __syncthreads();
  }
}

// ---------------- phase 1b: merge chunk partials (values) -------------------
__global__ void merge_parts_kernel() {
  int t = blockIdx.x * blockDim.x + threadIdx.x;
  if (t >= NB * NG) return;
  float best[4] = {0.0f, 0.0f, 0.0f, 0.0f};
  for (int c = 0; c < NCHUNK; c++) {
    merge4f(best, &g_partf[(size_t)(t * NCHUNK + c) * 4]);
  }
  int b = t >> 6, g = t & 63;
#pragma unroll
  for (int k = 0; k < 4; k++) g_topval[b][g][k] = best[k];
}

// ---------------- phase 2: anchor-major labeling + positives + index recovery
// grid: x = anchor blocks (782), y = image (8)
__global__ void __launch_bounds__(256) phase2_kernel(const float *__restrict__ anchors,
                                                     const float *__restrict__ gt,
                                                     SplitKeys sk) {
  const int b = blockIdx.y;
  const int tid = threadIdx.x;
  __shared__ float4 sbox[NG];
  __shared__ float4 sah[NG];  // (area, hq, v3, unused)
  if (tid < NG) {
    const float *gp = gt + (size_t)(b * NG + tid) * 4;
    float cx = gp[0], cy = gp[1], w = gp[2], h = gp[3];
    float tx = __fmul_rn(0.5f, w), ty = __fmul_rn(0.5f, h);
    float x1 = __fsub_rn(cx, tx), x2 = __fadd_rn(cx, tx);
    float y1 = __fsub_rn(cy, ty), y2 = __fadd_rn(cy, ty);
    sbox[tid] = make_float4(x1, y1, x2, y2);
    sah[tid] = make_float4(__fmul_rn(__fsub_rn(x2, x1), __fsub_rn(y2, y1)),
                           g_topval[b][tid][0], g_topval[b][tid][3], 0.0f);
  }
  __syncthreads();
  int a = blockIdx.x * 256 + tid;
  if (a >= NA) return;  // NA % 32 == 0 -> warp-uniform exit, ballot below safe

  float4 v = reinterpret_cast<const float4 *>(anchors)[(size_t)b * NA + a];
  float tx = __fmul_rn(0.5f, v.z), ty = __fmul_rn(0.5f, v.w);
  float ax1 = __fsub_rn(v.x, tx), ax2 = __fadd_rn(v.x, tx);
  float ay1 = __fsub_rn(v.y, ty), ay2 = __fadd_rn(v.y, ty);
  float aa = __fmul_rn(__fsub_rn(ax2, ax1), __fsub_rn(ay2, ay1));

  float best = -1.0f;
  int bg = 0;
  bool eq = false;
#pragma unroll 8
  for (int g = 0; g < NG; g++) {
    float4 gb = sbox[g];
    float4 ah = sah[g];
    float ltx = fmaxf(gb.x, ax1);
    float lty = fmaxf(gb.y, ay1);
    float rbx = fminf(gb.z, ax2);
    float rby = fminf(gb.w, ay2);
    float wx = fmaxf(__fsub_rn(rbx, ltx), 0.0f);
    float wy = fmaxf(__fsub_rn(rby, lty), 0.0f);
    float inter = __fmul_rn(wx, wy);
    if (inter == 0.0f) continue;  // iou 0: no top4 (v3>0), no eq (hq>0), argmax slot irrelevant
    float uni = __fsub_rn(__fadd_rn(ah.x, aa), inter);
    float iou = __fdiv_rn(inter, uni);
    eq |= (iou == ah.y);                     // low-quality match (exact equality)
    if (iou > best) { best = iou; bg = g; }  // first-max == jnp.argmax
    if (iou >= ah.z) {                       // top-4 candidate: recover index here
      int slot = atomicAdd(&g_candcnt[b][g], 1);
      if (slot < CAND_MAX)
        g_cand[b][g][slot] = ((unsigned long long)__float_as_uint(iou) << 32) |
                             (0xFFFFFFFFu - (unsigned int)a);
    }
  }
  bool pos = (best >= 0.7f) || eq;

  // warp-aggregated append of subsample keys for positives
  unsigned int mask = __ballot_sync(0xFFFFFFFFu, pos);
  if (pos) {
    // JAX partitionable uniform bits: (o0,o1)=threefry(key_b,(0,a)); bits = o0^o1
    unsigned int o0, o1;
    threefry2x32(sk.k[2 * b], sk.k[2 * b + 1], 0u, (unsigned int)a, o0, o1);
    unsigned int u = o0 ^ o1;
    float f = __uint_as_float((u >> 9) | 0x3f800000u);
    unsigned int rb = __float_as_uint(__fsub_rn(f, 1.0f));  // exact: f in [1,2)
    unsigned long long key =
        ((unsigned long long)rb << 32) | (unsigned int)(a * 64 + bg);
    int lane = tid & 31;
    int leader = __ffs(mask) - 1;
    int base = 0;
    if (lane == leader) base = atomicAdd(&g_npos[b], __popc(mask));
    base = __shfl_sync(mask, base, leader);
    int off = __popc(mask & ((1u << lane) - 1u));
    g_poskeys[b][base + off] = key;
  }
}

// ---------------- phase 2b: finalize top-4 indices from candidates ----------
__global__ void cand_select_kernel() {
  int t = blockIdx.x * blockDim.x + threadIdx.x;
  if (t >= NB * NG) return;
  int b = t >> 6, g = t & 63;
  int cnt = g_candcnt[b][g];
  if (cnt > CAND_MAX) cnt = CAND_MAX;
  unsigned long long best[4] = {0ull, 0ull, 0ull, 0ull};
  for (int i = 0; i < cnt; i++) {
    unsigned long long key = g_cand[b][g][i];
    if (key > best[3]) insert4(best, key);
  }
#pragma unroll
  for (int k = 0; k < 4; k++)
    g_topidx[b][g][k] = (int)(0xFFFFFFFFu - (unsigned int)best[k]);
}

// ---------------- phase 3: select 128 smallest keys, count per GT -----------
__global__ void __launch_bounds__(1024) phase3_kernel() {
  const int b = blockIdx.x;
  const int tid = threadIdx.x;
  const int n = g_npos[b];
  __shared__ int hist[256];
  __shared__ unsigned long long s_prefix;
  __shared__ int s_want;

  unsigned long long thresh;
  if (n <= MAXPOS) {
    thresh = ~0ull;  // select all positives
  } else {
    if (tid == 0) { s_prefix = 0ull; s_want = MAXPOS; }
    __syncthreads();
    for (int shift = 56; shift >= 0; shift -= 8) {
      if (tid < 256) hist[tid] = 0;
      __syncthreads();
      unsigned long long pref = s_prefix;
      for (int i = tid; i < n; i += 1024) {
        unsigned long long k = g_poskeys[b][i];
        bool match = (shift == 56) ? true
                                   : ((k >> (shift + 8)) == (pref >> (shift + 8)));
        if (match) atomicAdd(&hist[(int)((k >> shift) & 255u)], 1);
      }
      __syncthreads();
      if (tid == 0) {
        int want = s_want;
        int d = 0;
        for (; d < 256; d++) {
          if (want <= hist[d]) break;
          want -= hist[d];
        }
        s_prefix = pref | ((unsigned long long)d << shift);
        s_want = want;
      }
      __syncthreads();
    }
    thresh = s_prefix;  // exact 128th-smallest key (keys unique)
  }

  __shared__ int cnt[NG];
  if (tid < NG) cnt[tid] = 0;
  __syncthreads();
  for (int i = tid; i < n; i += 1024) {
    unsigned long long k = g_poskeys[b][i];
    if (k <= thresh) atomicAdd(&cnt[(int)(k & 63u)], 1);
  }
  __syncthreads();
  if (tid < NG) g_counts[b][tid] = cnt[tid];
}

// ---------------- phase 4: emit [pr | gt | valid | scores] as float32 -------
__global__ void write_out_kernel(float *__restrict__ out) {
  int t = blockIdx.x * blockDim.x + threadIdx.x;
  if (t >= NB * NG * NK) return;
  int b = t >> 8;
  int g = (t >> 2) & 63;
  int k = t & 3;
  int c = g_counts[b][g];
  if (c > NK) c = NK;
  bool valid = k < c;
  float val = g_topval[b][g][k];
  int idx = g_topidx[b][g][k];
  const int SEC = NB * NG * NK;  // 2048
  int o = b * (NG * NK) + g * NK + k;
  out[o]           = valid ? (float)idx : -1.0f;
  out[SEC + o]     = valid ? (float)g : -1.0f;
  out[2 * SEC + o] = valid ? 1.0f : 0.0f;
  out[3 * SEC + o] = valid ? val : 0.0f;
}

// ---------------- launch -----------------------------------------------------
extern "C" void kernel_launch(void *const *d_in, const int *in_sizes, int n_in,
                              void *d_out, int out_size) {
  const float *anchors = (const float *)d_in[0];   // [8, 200000, 4] cxcywh
  const float *gt      = (const float *)d_in[1];   // [8, 64, 4] cxcywh

  // JAX partitionable split (foldlike): key_b = threefry((0,42), (0,b)), both words
  SplitKeys sk;
  for (int b = 0; b < NB; b++) {
    unsigned int o0, o1;
    threefry2x32(0u, 42u, 0u, (unsigned int)b, o0, o1);
    sk.k[2 * b] = o0;
    sk.k[2 * b + 1] = o1;
  }

  init_kernel<<<2, 256>>>();
  phase1_kernel<<<dim3(NCHUNK, NG / GQ, NB), 256>>>(anchors, gt);
  merge_parts_kernel<<<2, 256>>>();
  phase2_kernel<<<dim3((NA + 255) / 256, NB), 256>>>(anchors, gt, sk);
  cand_select_kernel<<<2, 256>>>();
  phase3_kernel<<<NB, 1024>>>();
  write_out_kernel<<<NB, 256>>>((float *)d_out);
}

// round 9
// speedup vs baseline: 2.2313x; 1.6323x over previous
#include <cuda_runtime.h>
#include <stdint.h>

#define NB 8
#define NA 200000
#define NG 64
#define NK 4
#define NCHUNK 8
#define CHUNK 25000
#define GQ 4
#define MAXPOS 128
#define CAND_MAX 128
#define FIXB 32
#define THR_SAFE 0.699990f   // 0.7 minus margin >> 2ulp fdividef error
#define V3_SHRINK 0.99999f   // relative margin on v3 threshold

// ---------------- scratch (static __device__, no allocation) ----------------
__device__ float g_partf[NB * NG * NCHUNK * NK];  // chunk-partial approx top4 values
__device__ float g_v3safe[NB][NG];                // shrunk 4th-best (candidate threshold)
__device__ float g_topval[NB][NG][NK];            // EXACT top4 values (from candidates)
__device__ int   g_topidx[NB][NG][NK];            // EXACT top4 indices
__device__ unsigned long long g_cand[NB][NG][CAND_MAX];  // exact (val, ~idx) keys
__device__ int g_candcnt[NB][NG];
__device__ int g_flagged[NB][NA];                 // compact list of suspect anchors
__device__ int g_flagcnt[NB];
__device__ unsigned long long g_poskeys[NB][NA];
__device__ int g_npos[NB];
__device__ int g_counts[NB][NG];

struct SplitKeys { unsigned int k[2 * NB]; };

// ---------------- threefry2x32 (exact JAX kernel: 20 rounds) ----------------
__host__ __device__ inline void threefry2x32(unsigned int k0, unsigned int k1,
                                             unsigned int c0, unsigned int c1,
                                             unsigned int &o0, unsigned int &o1) {
  unsigned int ks2 = 0x1BD11BDAu ^ k0 ^ k1;
  unsigned int x0 = c0 + k0, x1 = c1 + k1;
#define TFR(r) do { x0 += x1; x1 = (x1 << (r)) | (x1 >> (32 - (r))); x1 ^= x0; } while (0)
  TFR(13); TFR(15); TFR(26); TFR(6);
  x0 += k1;  x1 += ks2 + 1u;
  TFR(17); TFR(29); TFR(16); TFR(24);
  x0 += ks2; x1 += k0 + 2u;
  TFR(13); TFR(15); TFR(26); TFR(6);
  x0 += k0;  x1 += k1 + 3u;
  TFR(17); TFR(29); TFR(16); TFR(24);
  x0 += k1;  x1 += ks2 + 4u;
  TFR(13); TFR(15); TFR(26); TFR(6);
  x0 += ks2; x1 += k0 + 5u;
#undef TFR
  o0 = x0; o1 = x1;
}

// insert u64 key into descending sorted 4-list; caller guarantees key > t[3]
__device__ __forceinline__ void insert4(unsigned long long *t, unsigned long long key) {
  if (key > t[1]) {
    t[3] = t[2]; t[2] = t[1];
    if (key > t[0]) { t[1] = t[0]; t[0] = key; } else { t[1] = key; }
  } else {
    if (key > t[2]) { t[3] = t[2]; t[2] = key; } else { t[3] = key; }
  }
}

// merge two descending sorted float 4-lists -> top4 into a
__device__ __forceinline__ void merge4f(float *a, const float *b) {
  float out[4];
  int i = 0, j = 0;
#pragma unroll
  for (int k = 0; k < 4; k++) {
    float av = a[i], bv = b[j];
    if (av >= bv) { out[k] = av; i++; } else { out[k] = bv; j++; }
  }
#pragma unroll
  for (int k = 0; k < 4; k++) a[k] = out[k];
}

__global__ void init_kernel() {
  int t = threadIdx.x + blockIdx.x * blockDim.x;
  if (t < NB) { g_npos[t] = 0; g_flagcnt[t] = 0; }
  if (t < NB * NG) ((int *)g_candcnt)[t] = 0;
}

// ---------------- phase 1: per-GT APPROX top-4 values (GT-major) ------------
// grid: x = anchor chunk (8), y = gt group (16 groups of 4), z = image (8)
__global__ void __launch_bounds__(256) phase1_kernel(const float *__restrict__ anchors,
                                                     const float *__restrict__ gt) {
  const int b = blockIdx.z;
  const int g0 = blockIdx.y * GQ;
  const int ch = blockIdx.x;
  const int tid = threadIdx.x;

  __shared__ float sg[GQ][5];
  if (tid < GQ) {
    const float *gp = gt + (size_t)(b * NG + g0 + tid) * 4;
    float cx = gp[0], cy = gp[1], w = gp[2], h = gp[3];
    float tx = __fmul_rn(0.5f, w), ty = __fmul_rn(0.5f, h);
    float x1 = __fsub_rn(cx, tx), x2 = __fadd_rn(cx, tx);
    float y1 = __fsub_rn(cy, ty), y2 = __fadd_rn(cy, ty);
    sg[tid][0] = x1; sg[tid][1] = y1; sg[tid][2] = x2; sg[tid][3] = y2;
    sg[tid][4] = __fmul_rn(__fsub_rn(x2, x1), __fsub_rn(y2, y1));
  }
  __syncthreads();

  float gx1[GQ], gy1[GQ], gx2[GQ], gy2[GQ], ga[GQ];
#pragma unroll
  for (int j = 0; j < GQ; j++) {
    gx1[j] = sg[j][0]; gy1[j] = sg[j][1]; gx2[j] = sg[j][2]; gy2[j] = sg[j][3]; ga[j] = sg[j][4];
  }

  float t0[GQ], t1[GQ], t2[GQ], t3[GQ];
#pragma unroll
  for (int j = 0; j < GQ; j++) { t0[j] = 0.0f; t1[j] = 0.0f; t2[j] = 0.0f; t3[j] = 0.0f; }

  const int a0 = ch * CHUNK;
  const float4 *ap = reinterpret_cast<const float4 *>(anchors) + (size_t)b * NA;
  for (int a = a0 + tid; a < a0 + CHUNK; a += 256) {
    float4 v = ap[a];
    float tx = __fmul_rn(0.5f, v.z), ty = __fmul_rn(0.5f, v.w);
    float ax1 = __fsub_rn(v.x, tx), ax2 = __fadd_rn(v.x, tx);
    float ay1 = __fsub_rn(v.y, ty), ay2 = __fadd_rn(v.y, ty);
    float aa = __fmul_rn(__fsub_rn(ax2, ax1), __fsub_rn(ay2, ay1));
#pragma unroll
    for (int j = 0; j < GQ; j++) {
      float ltx = fmaxf(gx1[j], ax1);
      float lty = fmaxf(gy1[j], ay1);
      float rbx = fminf(gx2[j], ax2);
      float rby = fminf(gy2[j], ay2);
      float wx = fmaxf(__fsub_rn(rbx, ltx), 0.0f);
      float wy = fmaxf(__fsub_rn(rby, lty), 0.0f);
      float inter = __fmul_rn(wx, wy);
      float uni = __fsub_rn(__fadd_rn(ga[j], aa), inter);
      float iou = __fdividef(inter, uni);  // approx (<=2ulp); 0 when inter==0
      // branchless sorted-desc top4 insert: 7 FMNMX
      float m0 = fmaxf(t0[j], iou), n0 = fminf(t0[j], iou);
      float m1 = fmaxf(t1[j], n0),  n1 = fminf(t1[j], n0);
      float m2 = fmaxf(t2[j], n1),  n2 = fminf(t2[j], n1);
      float m3 = fmaxf(t3[j], n2);
      t0[j] = m0; t1[j] = m1; t2[j] = m2; t3[j] = m3;
    }
  }

  __shared__ float red[256 * 4];
  for (int j = 0; j < GQ; j++) {
    red[tid * 4 + 0] = t0[j];
    red[tid * 4 + 1] = t1[j];
    red[tid * 4 + 2] = t2[j];
    red[tid * 4 + 3] = t3[j];
    __syncthreads();
    for (int s = 128; s > 0; s >>= 1) {
      if (tid < s) merge4f(&red[tid * 4], &red[(tid + s) * 4]);
      __syncthreads();
    }
    if (tid == 0) {
      size_t base = (size_t)((b * NG + g0 + j) * NCHUNK + ch) * 4;
#pragma unroll
      for (int k = 0; k < 4; k++) g_partf[base + k] = red[k];
    }
    __syncthreads();
  }
}

// ---------------- phase 1b: merge chunk partials -> shrunk v3 threshold -----
__global__ void merge_parts_kernel() {
  int t = blockIdx.x * blockDim.x + threadIdx.x;
  if (t >= NB * NG) return;
  float best[4] = {0.0f, 0.0f, 0.0f, 0.0f};
  for (int c = 0; c < NCHUNK; c++) {
    merge4f(best, &g_partf[(size_t)(t * NCHUNK + c) * 4]);
  }
  int b = t >> 6, g = t & 63;
  // shrink for approx error; floor keeps inter==0 pairs (approx 0) excluded
  g_v3safe[b][g] = fmaxf(__fmul_rn(best[3], V3_SHRINK), 1e-35f);
}

// ---------------- phase 2: approx sweep -> candidates + flagged anchors -----
// grid: x = anchor blocks (782), y = image (8)
__global__ void __launch_bounds__(256) phase2_kernel(const float *__restrict__ anchors,
                                                     const float *__restrict__ gt) {
  const int b = blockIdx.y;
  const int tid = threadIdx.x;
  __shared__ float4 sbox[NG];
  __shared__ float2 sav[NG];  // (area, v3safe)
  if (tid < NG) {
    const float *gp = gt + (size_t)(b * NG + tid) * 4;
    float cx = gp[0], cy = gp[1], w = gp[2], h = gp[3];
    float tx = __fmul_rn(0.5f, w), ty = __fmul_rn(0.5f, h);
    float x1 = __fsub_rn(cx, tx), x2 = __fadd_rn(cx, tx);
    float y1 = __fsub_rn(cy, ty), y2 = __fadd_rn(cy, ty);
    sbox[tid] = make_float4(x1, y1, x2, y2);
    sav[tid] = make_float2(__fmul_rn(__fsub_rn(x2, x1), __fsub_rn(y2, y1)),
                           g_v3safe[b][tid]);
  }
  __syncthreads();
  int a = blockIdx.x * 256 + tid;
  if (a >= NA) return;  // NA % 32 == 0 -> warp-uniform exit, ballots below safe

  float4 v = reinterpret_cast<const float4 *>(anchors)[(size_t)b * NA + a];
  float tx = __fmul_rn(0.5f, v.z), ty = __fmul_rn(0.5f, v.w);
  float ax1 = __fsub_rn(v.x, tx), ax2 = __fadd_rn(v.x, tx);
  float ay1 = __fsub_rn(v.y, ty), ay2 = __fadd_rn(v.y, ty);
  float aa = __fmul_rn(__fsub_rn(ax2, ax1), __fsub_rn(ay2, ay1));

  float bestA = 0.0f;
  bool anyc = false;
#pragma unroll 8
  for (int g = 0; g < NG; g++) {
    float4 gb = sbox[g];
    float2 av2 = sav[g];
    float ltx = fmaxf(gb.x, ax1);
    float lty = fmaxf(gb.y, ay1);
    float rbx = fminf(gb.z, ax2);
    float rby = fminf(gb.w, ay2);
    float wx = fmaxf(__fsub_rn(rbx, ltx), 0.0f);
    float wy = fmaxf(__fsub_rn(rby, lty), 0.0f);
    float inter = __fmul_rn(wx, wy);
    float uni = __fsub_rn(__fadd_rn(av2.x, aa), inter);
    float iou_a = __fdividef(inter, uni);  // approx; 0 when inter==0
    bestA = fmaxf(bestA, iou_a);
    if (iou_a >= av2.y) {  // rare: possible top-4 member -> record EXACT key
      float iou_ex = __fdiv_rn(inter, uni);
      int slot = atomicAdd(&g_candcnt[b][g], 1);
      if (slot < CAND_MAX)
        g_cand[b][g][slot] = ((unsigned long long)__float_as_uint(iou_ex) << 32) |
                             (0xFFFFFFFFu - (unsigned int)a);
      anyc = true;
    }
  }
  // flag anchors that might be positive: near/above 0.7, or candidate (covers eq)
  bool flag = anyc || (bestA >= THR_SAFE);
  unsigned int mask = __ballot_sync(0xFFFFFFFFu, flag);
  if (flag) {
    int lane = tid & 31;
    int leader = __ffs(mask) - 1;
    int base = 0;
    if (lane == leader) base = atomicAdd(&g_flagcnt[b], __popc(mask));
    base = __shfl_sync(mask, base, leader);
    g_flagged[b][base + __popc(mask & ((1u << lane) - 1u))] = a;
  }
}

// ---------------- phase 2b: exact top-4 (values + indices) from candidates --
__global__ void cand_select_kernel() {
  int t = blockIdx.x * blockDim.x + threadIdx.x;
  if (t >= NB * NG) return;
  int b = t >> 6, g = t & 63;
  int cnt = g_candcnt[b][g];
  if (cnt > CAND_MAX) cnt = CAND_MAX;
  unsigned long long best[4] = {0ull, 0ull, 0ull, 0ull};
  for (int i = 0; i < cnt; i++) {
    unsigned long long key = g_cand[b][g][i];
    if (key > best[3]) insert4(best, key);
  }
#pragma unroll
  for (int k = 0; k < 4; k++) {
    g_topval[b][g][k] = __uint_as_float((unsigned int)(best[k] >> 32));
    g_topidx[b][g][k] = (int)(0xFFFFFFFFu - (unsigned int)best[k]);
  }
}

// ---------------- phase 2c: exact positive detection on flagged anchors -----
// grid: (FIXB, NB)
__global__ void __launch_bounds__(256) fixup_kernel(const float *__restrict__ anchors,
                                                    const float *__restrict__ gt,
                                                    SplitKeys sk) {
  const int b = blockIdx.y;
  const int tid = threadIdx.x;
  __shared__ float4 sbox[NG];
  __shared__ float2 sah[NG];  // (area, hq exact)
  if (tid < NG) {
    const float *gp = gt + (size_t)(b * NG + tid) * 4;
    float cx = gp[0], cy = gp[1], w = gp[2], h = gp[3];
    float tx = __fmul_rn(0.5f, w), ty = __fmul_rn(0.5f, h);
    float x1 = __fsub_rn(cx, tx), x2 = __fadd_rn(cx, tx);
    float y1 = __fsub_rn(cy, ty), y2 = __fadd_rn(cy, ty);
    sbox[tid] = make_float4(x1, y1, x2, y2);
    sah[tid] = make_float2(__fmul_rn(__fsub_rn(x2, x1), __fsub_rn(y2, y1)),
                           g_topval[b][tid][0]);
  }
  __syncthreads();

  const int n = g_flagcnt[b];
  const int step = FIXB * 256;
  const int rounds = (n + step - 1) / step;  // uniform across block
  for (int r = 0; r < rounds; r++) {
    int i = blockIdx.x * 256 + tid + r * step;
    bool active = i < n;
    bool pos = false;
    int a = 0, bg = 0;
    if (active) {
      a = g_flagged[b][i];
      float4 v = reinterpret_cast<const float4 *>(anchors)[(size_t)b * NA + a];
      float tx = __fmul_rn(0.5f, v.z), ty = __fmul_rn(0.5f, v.w);
      float ax1 = __fsub_rn(v.x, tx), ax2 = __fadd_rn(v.x, tx);
      float ay1 = __fsub_rn(v.y, ty), ay2 = __fadd_rn(v.y, ty);
      float aa = __fmul_rn(__fsub_rn(ax2, ax1), __fsub_rn(ay2, ay1));
      float best = -1.0f;
      bool eq = false;
      for (int g = 0; g < NG; g++) {
        float4 gb = sbox[g];
        float2 ah = sah[g];
        float ltx = fmaxf(gb.x, ax1);
        float lty = fmaxf(gb.y, ay1);
        float rbx = fminf(gb.z, ax2);
        float rby = fminf(gb.w, ay2);
        float wx = fmaxf(__fsub_rn(rbx, ltx), 0.0f);
        float wy = fmaxf(__fsub_rn(rby, lty), 0.0f);
        float inter = __fmul_rn(wx, wy);
        if (inter == 0.0f) continue;  // exact 0: can't hit 0.7, can't equal hq>0
        float uni = __fsub_rn(__fadd_rn(ah.x, aa), inter);
        float iou = __fdiv_rn(inter, uni);
        eq |= (iou == ah.y);                     // low-quality match (exact)
        if (iou > best) { best = iou; bg = g; }  // first-max == jnp.argmax
      }
      pos = (best >= 0.7f) || eq;
    }
    unsigned int mask = __ballot_sync(0xFFFFFFFFu, active && pos);
    if (active && pos) {
      unsigned int o0, o1;
      threefry2x32(sk.k[2 * b], sk.k[2 * b + 1], 0u, (unsigned int)a, o0, o1);
      unsigned int u = o0 ^ o1;
      float f = __uint_as_float((u >> 9) | 0x3f800000u);
      unsigned int rb = __float_as_uint(__fsub_rn(f, 1.0f));  // exact: f in [1,2)
      unsigned long long key =
          ((unsigned long long)rb << 32) | (unsigned int)(a * 64 + bg);
      int lane = tid & 31;
      int leader = __ffs(mask) - 1;
      int base = 0;
      if (lane == leader) base = atomicAdd(&g_npos[b], __popc(mask));
      base = __shfl_sync(mask, base, leader);
      g_poskeys[b][base + __popc(mask & ((1u << lane) - 1u))] = key;
    }
  }
}

// ---------------- phase 3: select 128 smallest keys, count per GT -----------
__global__ void __launch_bounds__(1024) phase3_kernel() {
  const int b = blockIdx.x;
  const int tid = threadIdx.x;
  const int n = g_npos[b];
  __shared__ int hist[256];
  __shared__ unsigned long long s_prefix;
  __shared__ int s_want;

  unsigned long long thresh;
  if (n <= MAXPOS) {
    thresh = ~0ull;  // select all positives
  } else {
    if (tid == 0) { s_prefix = 0ull; s_want = MAXPOS; }
    __syncthreads();
    for (int shift = 56; shift >= 0; shift -= 8) {
      if (tid < 256) hist[tid] = 0;
      __syncthreads();
      unsigned long long pref = s_prefix;
      for (int i = tid; i < n; i += 1024) {
        unsigned long long k = g_poskeys[b][i];
        bool match = (shift == 56) ? true
                                   : ((k >> (shift + 8)) == (pref >> (shift + 8)));
        if (match) atomicAdd(&hist[(int)((k >> shift) & 255u)], 1);
      }
      __syncthreads();
      if (tid == 0) {
        int want = s_want;
        int d = 0;
        for (; d < 256; d++) {
          if (want <= hist[d]) break;
          want -= hist[d];
        }
        s_prefix = pref | ((unsigned long long)d << shift);
        s_want = want;
      }
      __syncthreads();
    }
    thresh = s_prefix;  // exact 128th-smallest key (keys unique)
  }

  __shared__ int cnt[NG];
  if (tid < NG) cnt[tid] = 0;
  __syncthreads();
  for (int i = tid; i < n; i += 1024) {
    unsigned long long k = g_poskeys[b][i];
    if (k <= thresh) atomicAdd(&cnt[(int)(k & 63u)], 1);
  }
  __syncthreads();
  if (tid < NG) g_counts[b][tid] = cnt[tid];
}

// ---------------- phase 4: emit [pr | gt | valid | scores] as float32 -------
__global__ void write_out_kernel(float *__restrict__ out) {
  int t = blockIdx.x * blockDim.x + threadIdx.x;
  if (t >= NB * NG * NK) return;
  int b = t >> 8;
  int g = (t >> 2) & 63;
  int k = t & 3;
  int c = g_counts[b][g];
  if (c > NK) c = NK;
  bool valid = k < c;
  float val = g_topval[b][g][k];
  int idx = g_topidx[b][g][k];
  const int SEC = NB * NG * NK;  // 2048
  int o = b * (NG * NK) + g * NK + k;
  out[o]           = valid ? (float)idx : -1.0f;
  out[SEC + o]     = valid ? (float)g : -1.0f;
  out[2 * SEC + o] = valid ? 1.0f : 0.0f;
  out[3 * SEC + o] = valid ? val : 0.0f;
}

// ---------------- launch -----------------------------------------------------
extern "C" void kernel_launch(void *const *d_in, const int *in_sizes, int n_in,
                              void *d_out, int out_size) {
  const float *anchors = (const float *)d_in[0];   // [8, 200000, 4] cxcywh
  const float *gt      = (const float *)d_in[1];   // [8, 64, 4] cxcywh

  // JAX partitionable split (foldlike): key_b = threefry((0,42), (0,b)), both words
  SplitKeys sk;
  for (int b = 0; b < NB; b++) {
    unsigned int o0, o1;
    threefry2x32(0u, 42u, 0u, (unsigned int)b, o0, o1);
    sk.k[2 * b] = o0;
    sk.k[2 * b + 1] = o1;
  }

  init_kernel<<<2, 256>>>();
  phase1_kernel<<<dim3(NCHUNK, NG / GQ, NB), 256>>>(anchors, gt);
  merge_parts_kernel<<<2, 256>>>();
  phase2_kernel<<<dim3((NA + 255) / 256, NB), 256>>>(anchors, gt);
  cand_select_kernel<<<2, 256>>>();
  fixup_kernel<<<dim3(FIXB, NB), 256>>>(anchors, gt, sk);
  phase3_kernel<<<NB, 1024>>>();
  write_out_kernel<<<NB, 256>>>((float *)d_out);
}

// round 10
// speedup vs baseline: 2.6399x; 1.1831x over previous
#include <cuda_runtime.h>
#include <stdint.h>

#define NB 8
#define NA 200000
#define NG 64
#define NK 4
#define NCHUNK 8
#define CHUNK 25000
#define GQ 4
#define MAXPOS 128
#define CAND_MAX 512
#define FIXB 32
#define THR_SAFE 0.699990f   // 0.7 minus margin >> rounding error
#define V3_SHRINK 0.99999f   // relative margin on v3 threshold

// ---------------- scratch (static __device__, no allocation) ----------------
__device__ float g_partf[NB * NG * NCHUNK * 4];   // chunk-partial 4-slot maxima
__device__ float g_v3safe[NB][NG];                // shrunk threshold (<= exact v3)
__device__ float g_topval[NB][NG][NK];            // EXACT top4 values (from candidates)
__device__ int   g_topidx[NB][NG][NK];            // EXACT top4 indices
__device__ unsigned long long g_cand[NB][NG][CAND_MAX];  // exact (val, ~idx) keys
__device__ int g_candcnt[NB][NG];
__device__ int g_flagged[NB][NA];                 // compact list of suspect anchors
__device__ int g_flagcnt[NB];
__device__ unsigned long long g_poskeys[NB][NA];
__device__ int g_npos[NB];
__device__ int g_counts[NB][NG];

struct SplitKeys { unsigned int k[2 * NB]; };

// ---------------- threefry2x32 (exact JAX kernel: 20 rounds) ----------------
__host__ __device__ inline void threefry2x32(unsigned int k0, unsigned int k1,
                                             unsigned int c0, unsigned int c1,
                                             unsigned int &o0, unsigned int &o1) {
  unsigned int ks2 = 0x1BD11BDAu ^ k0 ^ k1;
  unsigned int x0 = c0 + k0, x1 = c1 + k1;
#define TFR(r) do { x0 += x1; x1 = (x1 << (r)) | (x1 >> (32 - (r))); x1 ^= x0; } while (0)
  TFR(13); TFR(15); TFR(26); TFR(6);
  x0 += k1;  x1 += ks2 + 1u;
  TFR(17); TFR(29); TFR(16); TFR(24);
  x0 += ks2; x1 += k0 + 2u;
  TFR(13); TFR(15); TFR(26); TFR(6);
  x0 += k0;  x1 += k1 + 3u;
  TFR(17); TFR(29); TFR(16); TFR(24);
  x0 += k1;  x1 += ks2 + 4u;
  TFR(13); TFR(15); TFR(26); TFR(6);
  x0 += ks2; x1 += k0 + 5u;
#undef TFR
  o0 = x0; o1 = x1;
}

// insert u64 key into descending sorted 4-list; caller guarantees key > t[3]
__device__ __forceinline__ void insert4(unsigned long long *t, unsigned long long key) {
  if (key > t[1]) {
    t[3] = t[2]; t[2] = t[1];
    if (key > t[0]) { t[1] = t[0]; t[0] = key; } else { t[1] = key; }
  } else {
    if (key > t[2]) { t[3] = t[2]; t[2] = key; } else { t[3] = key; }
  }
}

__global__ void init_kernel() {
  int t = threadIdx.x + blockIdx.x * blockDim.x;
  if (t < NB) { g_npos[t] = 0; g_flagcnt[t] = 0; }
  if (t < NB * NG) ((int *)g_candcnt)[t] = 0;
}

// ---------------- phase 1: per-GT 4-slot maxima (GT-major) ------------------
// Each anchor belongs to exactly one of 4 disjoint slots (unroll phase).
// min(4 global slot maxima) <= exact v3 (they are 4 distinct elements).
// grid: x = anchor chunk (8), y = gt group (16 groups of 4), z = image (8)
__global__ void __launch_bounds__(256) phase1_kernel(const float *__restrict__ anchors,
                                                     const float *__restrict__ gt) {
  const int b = blockIdx.z;
  const int g0 = blockIdx.y * GQ;
  const int ch = blockIdx.x;
  const int tid = threadIdx.x;

  __shared__ float sg[GQ][5];
  if (tid < GQ) {
    const float *gp = gt + (size_t)(b * NG + g0 + tid) * 4;
    float cx = gp[0], cy = gp[1], w = gp[2], h = gp[3];
    float tx = __fmul_rn(0.5f, w), ty = __fmul_rn(0.5f, h);
    float x1 = __fsub_rn(cx, tx), x2 = __fadd_rn(cx, tx);
    float y1 = __fsub_rn(cy, ty), y2 = __fadd_rn(cy, ty);
    sg[tid][0] = x1; sg[tid][1] = y1; sg[tid][2] = x2; sg[tid][3] = y2;
    sg[tid][4] = __fmul_rn(__fsub_rn(x2, x1), __fsub_rn(y2, y1));
  }
  __syncthreads();

  float gx1[GQ], gy1[GQ], gx2[GQ], gy2[GQ], ga[GQ];
#pragma unroll
  for (int j = 0; j < GQ; j++) {
    gx1[j] = sg[j][0]; gy1[j] = sg[j][1]; gx2[j] = sg[j][2]; gy2[j] = sg[j][3]; ga[j] = sg[j][4];
  }

  float m[GQ][4];
#pragma unroll
  for (int j = 0; j < GQ; j++)
#pragma unroll
    for (int s = 0; s < 4; s++) m[j][s] = 0.0f;

  const int a0 = ch * CHUNK;
  const int aend = a0 + CHUNK;
  const float4 *ap = reinterpret_cast<const float4 *>(anchors) + (size_t)b * NA;

  int a = a0 + tid;
  // main: 4 anchors per iteration, static slot per position
  for (; a + 768 < aend; a += 1024) {
#pragma unroll
    for (int s = 0; s < 4; s++) {
      float4 v = ap[a + s * 256];
      float tx = __fmul_rn(0.5f, v.z), ty = __fmul_rn(0.5f, v.w);
      float ax1 = __fsub_rn(v.x, tx), ax2 = __fadd_rn(v.x, tx);
      float ay1 = __fsub_rn(v.y, ty), ay2 = __fadd_rn(v.y, ty);
      float aa = __fmul_rn(__fsub_rn(ax2, ax1), __fsub_rn(ay2, ay1));
#pragma unroll
      for (int j = 0; j < GQ; j++) {
        float ltx = fmaxf(gx1[j], ax1);
        float lty = fmaxf(gy1[j], ay1);
        float rbx = fminf(gx2[j], ax2);
        float rby = fminf(gy2[j], ay2);
        float wx = fmaxf(__fsub_rn(rbx, ltx), 0.0f);
        float wy = fmaxf(__fsub_rn(rby, lty), 0.0f);
        float inter = __fmul_rn(wx, wy);
        float uni = __fsub_rn(__fadd_rn(ga[j], aa), inter);
        float iou = __fdividef(inter, uni);  // approx; 0 when inter==0
        m[j][s] = fmaxf(m[j][s], iou);
      }
    }
  }
  // tail: remaining anchors all feed slot 0 (slots stay disjoint)
  for (; a < aend; a += 256) {
    float4 v = ap[a];
    float tx = __fmul_rn(0.5f, v.z), ty = __fmul_rn(0.5f, v.w);
    float ax1 = __fsub_rn(v.x, tx), ax2 = __fadd_rn(v.x, tx);
    float ay1 = __fsub_rn(v.y, ty), ay2 = __fadd_rn(v.y, ty);
    float aa = __fmul_rn(__fsub_rn(ax2, ax1), __fsub_rn(ay2, ay1));
#pragma unroll
    for (int j = 0; j < GQ; j++) {
      float ltx = fmaxf(gx1[j], ax1);
      float lty = fmaxf(gy1[j], ay1);
      float rbx = fminf(gx2[j], ax2);
      float rby = fminf(gy2[j], ay2);
      float wx = fmaxf(__fsub_rn(rbx, ltx), 0.0f);
      float wy = fmaxf(__fsub_rn(rby, lty), 0.0f);
      float inter = __fmul_rn(wx, wy);
      float uni = __fsub_rn(__fadd_rn(ga[j], aa), inter);
      float iou = __fdividef(inter, uni);
      m[j][0] = fmaxf(m[j][0], iou);
    }
  }

  // block reduction: elementwise max over all 16 (j,s) accumulators at once
  __shared__ float red[256 * GQ * 4];
#pragma unroll
  for (int j = 0; j < GQ; j++)
#pragma unroll
    for (int s = 0; s < 4; s++) red[tid * 16 + j * 4 + s] = m[j][s];
  __syncthreads();
  for (int st = 128; st > 0; st >>= 1) {
    if (tid < st) {
#pragma unroll
      for (int k = 0; k < 16; k++)
        red[tid * 16 + k] = fmaxf(red[tid * 16 + k], red[(tid + st) * 16 + k]);
    }
    __syncthreads();
  }
  if (tid < 16) {
    int j = tid >> 2, s = tid & 3;
    g_partf[(size_t)((b * NG + g0 + j) * NCHUNK + ch) * 4 + s] = red[tid];
  }
}

// ---------------- phase 1b: slot-merge -> shrunk v3 threshold ---------------
__global__ void merge_parts_kernel() {
  int t = blockIdx.x * blockDim.x + threadIdx.x;
  if (t >= NB * NG) return;
  float sm[4] = {0.0f, 0.0f, 0.0f, 0.0f};
  for (int c = 0; c < NCHUNK; c++) {
    const float *p = &g_partf[(size_t)(t * NCHUNK + c) * 4];
#pragma unroll
    for (int s = 0; s < 4; s++) sm[s] = fmaxf(sm[s], p[s]);
  }
  float thr = fminf(fminf(sm[0], sm[1]), fminf(sm[2], sm[3]));  // <= exact v3
  int b = t >> 6, g = t & 63;
  // shrink for fdividef error; floor excludes inter==0 pairs
  g_v3safe[b][g] = fmaxf(__fmul_rn(thr, V3_SHRINK), 1e-35f);
}

// ---------------- phase 2: division-free suspect sweep ----------------------
// suspect_g: inter >= c_g * uni, c_g = min(v3safe_g, THR_SAFE). Covers exact
// top-4 members, best>=0.7 anchors, and eq anchors (eq attains hq >= v3).
// grid: x = anchor blocks (782), y = image (8)
__global__ void __launch_bounds__(256) phase2_kernel(const float *__restrict__ anchors,
                                                     const float *__restrict__ gt) {
  const int b = blockIdx.y;
  const int tid = threadIdx.x;
  __shared__ float4 sbox[NG];
  __shared__ float4 sinf[NG];  // (area, c_g, v3safe, 0)
  if (tid < NG) {
    const float *gp = gt + (size_t)(b * NG + tid) * 4;
    float cx = gp[0], cy = gp[1], w = gp[2], h = gp[3];
    float tx = __fmul_rn(0.5f, w), ty = __fmul_rn(0.5f, h);
    float x1 = __fsub_rn(cx, tx), x2 = __fadd_rn(cx, tx);
    float y1 = __fsub_rn(cy, ty), y2 = __fadd_rn(cy, ty);
    sbox[tid] = make_float4(x1, y1, x2, y2);
    float v3s = g_v3safe[b][tid];
    sinf[tid] = make_float4(__fmul_rn(__fsub_rn(x2, x1), __fsub_rn(y2, y1)),
                            fminf(v3s, THR_SAFE), v3s, 0.0f);
  }
  __syncthreads();
  int a = blockIdx.x * 256 + tid;
  if (a >= NA) return;  // NA % 32 == 0 -> warp-uniform exit, ballots below safe

  float4 v = reinterpret_cast<const float4 *>(anchors)[(size_t)b * NA + a];
  float tx = __fmul_rn(0.5f, v.z), ty = __fmul_rn(0.5f, v.w);
  float ax1 = __fsub_rn(v.x, tx), ax2 = __fadd_rn(v.x, tx);
  float ay1 = __fsub_rn(v.y, ty), ay2 = __fadd_rn(v.y, ty);
  float aa = __fmul_rn(__fsub_rn(ax2, ax1), __fsub_rn(ay2, ay1));

  bool flag = false;
#pragma unroll 8
  for (int g = 0; g < NG; g++) {
    float4 gb = sbox[g];
    float4 si = sinf[g];
    float ltx = fmaxf(gb.x, ax1);
    float lty = fmaxf(gb.y, ay1);
    float rbx = fminf(gb.z, ax2);
    float rby = fminf(gb.w, ay2);
    float wx = fmaxf(__fsub_rn(rbx, ltx), 0.0f);
    float wy = fmaxf(__fsub_rn(rby, lty), 0.0f);
    float inter = __fmul_rn(wx, wy);
    float uni = __fsub_rn(__fadd_rn(si.x, aa), inter);
    if (inter >= __fmul_rn(si.y, uni)) {  // rare (~0.3%/warp-iter)
      flag = true;
      float iou_ex = __fdiv_rn(inter, uni);
      if (iou_ex >= si.z) {  // exact top-4 candidate (superset)
        int slot = atomicAdd(&g_candcnt[b][g], 1);
        if (slot < CAND_MAX)
          g_cand[b][g][slot] = ((unsigned long long)__float_as_uint(iou_ex) << 32) |
                               (0xFFFFFFFFu - (unsigned int)a);
      }
    }
  }
  unsigned int mask = __ballot_sync(0xFFFFFFFFu, flag);
  if (flag) {
    int lane = tid & 31;
    int leader = __ffs(mask) - 1;
    int base = 0;
    if (lane == leader) base = atomicAdd(&g_flagcnt[b], __popc(mask));
    base = __shfl_sync(mask, base, leader);
    g_flagged[b][base + __popc(mask & ((1u << lane) - 1u))] = a;
  }
}

// ---------------- phase 2b: exact top-4 (values + indices) from candidates --
__global__ void cand_select_kernel() {
  int t = blockIdx.x * blockDim.x + threadIdx.x;
  if (t >= NB * NG) return;
  int b = t >> 6, g = t & 63;
  int cnt = g_candcnt[b][g];
  if (cnt > CAND_MAX) cnt = CAND_MAX;
  unsigned long long best[4] = {0ull, 0ull, 0ull, 0ull};
  for (int i = 0; i < cnt; i++) {
    unsigned long long key = g_cand[b][g][i];
    if (key > best[3]) insert4(best, key);
  }
#pragma unroll
  for (int k = 0; k < 4; k++) {
    g_topval[b][g][k] = __uint_as_float((unsigned int)(best[k] >> 32));
    g_topidx[b][g][k] = (int)(0xFFFFFFFFu - (unsigned int)best[k]);
  }
}

// ---------------- phase 2c: exact positive detection on flagged anchors -----
// grid: (FIXB, NB)
__global__ void __launch_bounds__(256) fixup_kernel(const float *__restrict__ anchors,
                                                    const float *__restrict__ gt,
                                                    SplitKeys sk) {
  const int b = blockIdx.y;
  const int tid = threadIdx.x;
  __shared__ float4 sbox[NG];
  __shared__ float2 sah[NG];  // (area, hq exact)
  if (tid < NG) {
    const float *gp = gt + (size_t)(b * NG + tid) * 4;
    float cx = gp[0], cy = gp[1], w = gp[2], h = gp[3];
    float tx = __fmul_rn(0.5f, w), ty = __fmul_rn(0.5f, h);
    float x1 = __fsub_rn(cx, tx), x2 = __fadd_rn(cx, tx);
    float y1 = __fsub_rn(cy, ty), y2 = __fadd_rn(cy, ty);
    sbox[tid] = make_float4(x1, y1, x2, y2);
    sah[tid] = make_float2(__fmul_rn(__fsub_rn(x2, x1), __fsub_rn(y2, y1)),
                           g_topval[b][tid][0]);
  }
  __syncthreads();

  const int n = g_flagcnt[b];
  const int step = FIXB * 256;
  const int rounds = (n + step - 1) / step;  // uniform across block
  for (int r = 0; r < rounds; r++) {
    int i = blockIdx.x * 256 + tid + r * step;
    bool active = i < n;
    bool pos = false;
    int a = 0, bg = 0;
    if (active) {
      a = g_flagged[b][i];
      float4 v = reinterpret_cast<const float4 *>(anchors)[(size_t)b * NA + a];
      float tx = __fmul_rn(0.5f, v.z), ty = __fmul_rn(0.5f, v.w);
      float ax1 = __fsub_rn(v.x, tx), ax2 = __fadd_rn(v.x, tx);
      float ay1 = __fsub_rn(v.y, ty), ay2 = __fadd_rn(v.y, ty);
      float aa = __fmul_rn(__fsub_rn(ax2, ax1), __fsub_rn(ay2, ay1));
      float best = -1.0f;
      bool eq = false;
      for (int g = 0; g < NG; g++) {
        float4 gb = sbox[g];
        float2 ah = sah[g];
        float ltx = fmaxf(gb.x, ax1);
        float lty = fmaxf(gb.y, ay1);
        float rbx = fminf(gb.z, ax2);
        float rby = fminf(gb.w, ay2);
        float wx = fmaxf(__fsub_rn(rbx, ltx), 0.0f);
        float wy = fmaxf(__fsub_rn(rby, lty), 0.0f);
        float inter = __fmul_rn(wx, wy);
        if (inter == 0.0f) continue;  // exact 0: can't hit 0.7, can't equal hq>0
        float uni = __fsub_rn(__fadd_rn(ah.x, aa), inter);
        float iou = __fdiv_rn(inter, uni);
        eq |= (iou == ah.y);                     // low-quality match (exact)
        if (iou > best) { best = iou; bg = g; }  // first-max == jnp.argmax
      }
      pos = (best >= 0.7f) || eq;
    }
    unsigned int mask = __ballot_sync(0xFFFFFFFFu, active && pos);
    if (active && pos) {
      unsigned int o0, o1;
      threefry2x32(sk.k[2 * b], sk.k[2 * b + 1], 0u, (unsigned int)a, o0, o1);
      unsigned int u = o0 ^ o1;
      float f = __uint_as_float((u >> 9) | 0x3f800000u);
      unsigned int rb = __float_as_uint(__fsub_rn(f, 1.0f));  // exact: f in [1,2)
      unsigned long long key =
          ((unsigned long long)rb << 32) | (unsigned int)(a * 64 + bg);
      int lane = tid & 31;
      int leader = __ffs(mask) - 1;
      int base = 0;
      if (lane == leader) base = atomicAdd(&g_npos[b], __popc(mask));
      base = __shfl_sync(mask, base, leader);
      g_poskeys[b][base + __popc(mask & ((1u << lane) - 1u))] = key;
    }
  }
}

// ---------------- phase 3: select 128 smallest keys, count per GT -----------
__global__ void __launch_bounds__(1024) phase3_kernel() {
  const int b = blockIdx.x;
  const int tid = threadIdx.x;
  const int n = g_npos[b];
  __shared__ int hist[256];
  __shared__ unsigned long long s_prefix;
  __shared__ int s_want;

  unsigned long long thresh;
  if (n <= MAXPOS) {
    thresh = ~0ull;  // select all positives
  } else {
    if (tid == 0) { s_prefix = 0ull; s_want = MAXPOS; }
    __syncthreads();
    for (int shift = 56; shift >= 0; shift -= 8) {
      if (tid < 256) hist[tid] = 0;
      __syncthreads();
      unsigned long long pref = s_prefix;
      for (int i = tid; i < n; i += 1024) {
        unsigned long long k = g_poskeys[b][i];
        bool match = (shift == 56) ? true
                                   : ((k >> (shift + 8)) == (pref >> (shift + 8)));
        if (match) atomicAdd(&hist[(int)((k >> shift) & 255u)], 1);
      }
      __syncthreads();
      if (tid == 0) {
        int want = s_want;
        int d = 0;
        for (; d < 256; d++) {
          if (want <= hist[d]) break;
          want -= hist[d];
        }
        s_prefix = pref | ((unsigned long long)d << shift);
        s_want = want;
      }
      __syncthreads();
    }
    thresh = s_prefix;  // exact 128th-smallest key (keys unique)
  }

  __shared__ int cnt[NG];
  if (tid < NG) cnt[tid] = 0;
  __syncthreads();
  for (int i = tid; i < n; i += 1024) {
    unsigned long long k = g_poskeys[b][i];
    if (k <= thresh) atomicAdd(&cnt[(int)(k & 63u)], 1);
  }
  __syncthreads();
  if (tid < NG) g_counts[b][tid] = cnt[tid];
}

// ---------------- phase 4: emit [pr | gt | valid | scores] as float32 -------
__global__ void write_out_kernel(float *__restrict__ out) {
  int t = blockIdx.x * blockDim.x + threadIdx.x;
  if (t >= NB * NG * NK) return;
  int b = t >> 8;
  int g = (t >> 2) & 63;
  int k = t & 3;
  int c = g_counts[b][g];
  if (c > NK) c = NK;
  bool valid = k < c;
  float val = g_topval[b][g][k];
  int idx = g_topidx[b][g][k];
  const int SEC = NB * NG * NK;  // 2048
  int o = b * (NG * NK) + g * NK + k;
  out[o]           = valid ? (float)idx : -1.0f;
  out[SEC + o]     = valid ? (float)g : -1.0f;
  out[2 * SEC + o] = valid ? 1.0f : 0.0f;
  out[3 * SEC + o] = valid ? val : 0.0f;
}

// ---------------- launch -----------------------------------------------------
extern "C" void kernel_launch(void *const *d_in, const int *in_sizes, int n_in,
                              void *d_out, int out_size) {
  const float *anchors = (const float *)d_in[0];   // [8, 200000, 4] cxcywh
  const float *gt      = (const float *)d_in[1];   // [8, 64, 4] cxcywh

  // JAX partitionable split (foldlike): key_b = threefry((0,42), (0,b)), both words
  SplitKeys sk;
  for (int b = 0; b < NB; b++) {
    unsigned int o0, o1;
    threefry2x32(0u, 42u, 0u, (unsigned int)b, o0, o1);
    sk.k[2 * b] = o0;
    sk.k[2 * b + 1] = o1;
  }

  init_kernel<<<2, 256>>>();
  phase1_kernel<<<dim3(NCHUNK, NG / GQ, NB), 256>>>(anchors, gt);
  merge_parts_kernel<<<2, 256>>>();
  phase2_kernel<<<dim3((NA + 255) / 256, NB), 256>>>(anchors, gt);
  cand_select_kernel<<<2, 256>>>();
  fixup_kernel<<<dim3(FIXB, NB), 256>>>(anchors, gt, sk);
  phase3_kernel<<<NB, 1024>>>();
  write_out_kernel<<<NB, 256>>>((float *)d_out);
}

// round 12
// speedup vs baseline: 2.6977x; 1.0219x over previous
#include <cuda_runtime.h>
#include <stdint.h>

#define NB 8
#define NA 200000
#define NG 64
#define NK 4
#define NCHUNK 16
#define CHUNK 12500
#define GQ 8
#define MAXPOS 128
#define CAND_MAX 512
#define POSB 32
#define KTHR 0.41174f        // q-space 0.7 threshold minus margin (0.7/1.7 = 0.4117647)

// ---------------- scratch (static __device__, no allocation) ----------------
__device__ float g_partq[NB * NG * NCHUNK * 4];   // chunk-partial 4-slot q maxima
__device__ float2 g_kp[NB][NG];                   // (kmin, kmin*area) primary threshold
__device__ float4 g_kp3[NB][NG];                  // (kv3, kv3*area, area, v3safe)
__device__ float g_topval[NB][NG][NK];            // EXACT top4 values
__device__ int   g_topidx[NB][NG][NK];            // EXACT top4 indices
__device__ unsigned long long g_cand[NB][NG][CAND_MAX];
__device__ int g_candcnt[NB][NG];
__device__ int g_flagged[NB][NA];                 // suspect anchors (compact)
__device__ unsigned long long g_fmask[NB][NA];    // per-suspect GT bitmask
__device__ int g_flagcnt[NB];
__device__ unsigned long long g_poskeys[NB][NA];
__device__ int g_npos[NB];
__device__ unsigned int g_sel[NB][MAXPOS];        // selected anchor ids
__device__ int g_nsel[NB];
__device__ int g_counts[NB][NG];

struct SplitKeys { unsigned int k[2 * NB]; };

// ---------------- threefry2x32 (exact JAX kernel: 20 rounds) ----------------
__host__ __device__ inline void threefry2x32(unsigned int k0, unsigned int k1,
                                             unsigned int c0, unsigned int c1,
                                             unsigned int &o0, unsigned int &o1) {
  unsigned int ks2 = 0x1BD11BDAu ^ k0 ^ k1;
  unsigned int x0 = c0 + k0, x1 = c1 + k1;
#define TFR(r) do { x0 += x1; x1 = (x1 << (r)) | (x1 >> (32 - (r))); x1 ^= x0; } while (0)
  TFR(13); TFR(15); TFR(26); TFR(6);
  x0 += k1;  x1 += ks2 + 1u;
  TFR(17); TFR(29); TFR(16); TFR(24);
  x0 += ks2; x1 += k0 + 2u;
  TFR(13); TFR(15); TFR(26); TFR(6);
  x0 += k0;  x1 += k1 + 3u;
  TFR(17); TFR(29); TFR(16); TFR(24);
  x0 += k1;  x1 += ks2 + 4u;
  TFR(13); TFR(15); TFR(26); TFR(6);
  x0 += ks2; x1 += k0 + 5u;
#undef TFR
  o0 = x0; o1 = x1;
}

// insert u64 key into descending sorted 4-list; caller guarantees key > t[3]
__device__ __forceinline__ void insert4(unsigned long long *t, unsigned long long key) {
  if (key > t[1]) {
    t[3] = t[2]; t[2] = t[1];
    if (key > t[0]) { t[1] = t[0]; t[0] = key; } else { t[1] = key; }
  } else {
    if (key > t[2]) { t[3] = t[2]; t[2] = key; } else { t[3] = key; }
  }
}

__global__ void init_kernel() {
  int t = threadIdx.x + blockIdx.x * blockDim.x;
  if (t < NB) { g_npos[t] = 0; g_flagcnt[t] = 0; g_nsel[t] = 0; }
  if (t < NB * NG) ((int *)g_candcnt)[t] = 0;
}

// ---------------- phase 1: per-GT 4-slot q maxima (GT-major) ----------------
// q = inter/(area_g + area_a) is a monotone transform of iou -> slot maxima in
// q-space give a valid v3 lower bound after conversion. No uni, no index work.
// grid: x = chunk (16), y = gt group (8 groups of 8), z = image (8)
__global__ void __launch_bounds__(256) phase1_kernel(const float *__restrict__ anchors,
                                                     const float *__restrict__ gt) {
  const int b = blockIdx.z;
  const int g0 = blockIdx.y * GQ;
  const int ch = blockIdx.x;
  const int tid = threadIdx.x;

  __shared__ float sg[GQ][5];
  if (tid < GQ) {
    const float *gp = gt + (size_t)(b * NG + g0 + tid) * 4;
    float cx = gp[0], cy = gp[1], w = gp[2], h = gp[3];
    float tx = __fmul_rn(0.5f, w), ty = __fmul_rn(0.5f, h);
    float x1 = __fsub_rn(cx, tx), x2 = __fadd_rn(cx, tx);
    float y1 = __fsub_rn(cy, ty), y2 = __fadd_rn(cy, ty);
    sg[tid][0] = x1; sg[tid][1] = y1; sg[tid][2] = x2; sg[tid][3] = y2;
    sg[tid][4] = __fmul_rn(__fsub_rn(x2, x1), __fsub_rn(y2, y1));
  }
  __syncthreads();

  float gx1[GQ], gy1[GQ], gx2[GQ], gy2[GQ], ga[GQ];
#pragma unroll
  for (int j = 0; j < GQ; j++) {
    gx1[j] = sg[j][0]; gy1[j] = sg[j][1]; gx2[j] = sg[j][2]; gy2[j] = sg[j][3]; ga[j] = sg[j][4];
  }

  float m[GQ][4];
#pragma unroll
  for (int j = 0; j < GQ; j++)
#pragma unroll
    for (int s = 0; s < 4; s++) m[j][s] = 0.0f;

  const int a0 = ch * CHUNK;
  const int aend = a0 + CHUNK;
  const float4 *ap = reinterpret_cast<const float4 *>(anchors) + (size_t)b * NA;

  int a = a0 + tid;
  for (; a + 768 < aend; a += 1024) {
#pragma unroll
    for (int s = 0; s < 4; s++) {
      float4 v = ap[a + s * 256];
      float tx = __fmul_rn(0.5f, v.z), ty = __fmul_rn(0.5f, v.w);
      float ax1 = __fsub_rn(v.x, tx), ax2 = __fadd_rn(v.x, tx);
      float ay1 = __fsub_rn(v.y, ty), ay2 = __fadd_rn(v.y, ty);
      float aa = __fmul_rn(__fsub_rn(ax2, ax1), __fsub_rn(ay2, ay1));
#pragma unroll
      for (int j = 0; j < GQ; j++) {
        float ltx = fmaxf(gx1[j], ax1);
        float lty = fmaxf(gy1[j], ay1);
        float rbx = fminf(gx2[j], ax2);
        float rby = fminf(gy2[j], ay2);
        float wx = fmaxf(__fsub_rn(rbx, ltx), 0.0f);
        float wy = fmaxf(__fsub_rn(rby, lty), 0.0f);
        float inter = __fmul_rn(wx, wy);
        float ssum = __fadd_rn(ga[j], aa);
        float q = __fdividef(inter, ssum);  // approx (<=2ulp), 0 when inter==0
        m[j][s] = fmaxf(m[j][s], q);
      }
    }
  }
  for (; a < aend; a += 256) {  // tail -> slot 0 (slots stay disjoint)
    float4 v = ap[a];
    float tx = __fmul_rn(0.5f, v.z), ty = __fmul_rn(0.5f, v.w);
    float ax1 = __fsub_rn(v.x, tx), ax2 = __fadd_rn(v.x, tx);
    float ay1 = __fsub_rn(v.y, ty), ay2 = __fadd_rn(v.y, ty);
    float aa = __fmul_rn(__fsub_rn(ax2, ax1), __fsub_rn(ay2, ay1));
#pragma unroll
    for (int j = 0; j < GQ; j++) {
      float ltx = fmaxf(gx1[j], ax1);
      float lty = fmaxf(gy1[j], ay1);
      float rbx = fminf(gx2[j], ax2);
      float rby = fminf(gy2[j], ay2);
      float wx = fmaxf(__fsub_rn(rbx, ltx), 0.0f);
      float wy = fmaxf(__fsub_rn(rby, lty), 0.0f);
      float inter = __fmul_rn(wx, wy);
      float ssum = __fadd_rn(ga[j], aa);
      float q = __fdividef(inter, ssum);
      m[j][0] = fmaxf(m[j][0], q);
    }
  }

  // block max-reduction of all 32 accumulators (stride 33 -> conflict-free)
  __shared__ float red[256 * 33];
#pragma unroll
  for (int j = 0; j < GQ; j++)
#pragma unroll
    for (int s = 0; s < 4; s++) red[tid * 33 + j * 4 + s] = m[j][s];
  __syncthreads();
  for (int st = 128; st > 0; st >>= 1) {
    if (tid < st) {
#pragma unroll
      for (int k = 0; k < 32; k++)
        red[tid * 33 + k] = fmaxf(red[tid * 33 + k], red[(tid + st) * 33 + k]);
    }
    __syncthreads();
  }
  if (tid < 32) {
    int j = tid >> 2, s = tid & 3;
    g_partq[(size_t)((b * NG + g0 + j) * NCHUNK + ch) * 4 + s] = red[j * 4 + s];
  }
}

// ---------------- phase 1b: merge -> q thresholds + iou-space v3safe --------
__global__ void merge_parts_kernel(const float *__restrict__ gt) {
  int t = blockIdx.x * blockDim.x + threadIdx.x;
  if (t >= NB * NG) return;
  float sm[4] = {0.0f, 0.0f, 0.0f, 0.0f};
  for (int c = 0; c < NCHUNK; c++) {
    const float *p = &g_partq[(size_t)(t * NCHUNK + c) * 4];
#pragma unroll
    for (int s = 0; s < 4; s++) sm[s] = fmaxf(sm[s], p[s]);
  }
  float thr_q = fminf(fminf(sm[0], sm[1]), fminf(sm[2], sm[3]));  // <= q(v3)+eps
  int b = t >> 6, g = t & 63;
  float kv3 = fmaxf(__fmul_rn(thr_q, 1.0f - 1e-5f), 1e-30f);
  float thr_iou = __fdividef(thr_q, __fsub_rn(1.0f, thr_q));  // q <= 0.5 -> safe
  float v3safe = fmaxf(__fmul_rn(thr_iou, 1.0f - 1e-5f), 1e-35f);
  float kmin = fminf(kv3, KTHR);

  const float *gp = gt + (size_t)(b * NG + g) * 4;
  float w = gp[2], h = gp[3];
  float tx = __fmul_rn(0.5f, w), ty = __fmul_rn(0.5f, h);
  float x1 = __fsub_rn(gp[0], tx), x2 = __fadd_rn(gp[0], tx);
  float y1 = __fsub_rn(gp[1], ty), y2 = __fadd_rn(gp[1], ty);
  float area = __fmul_rn(__fsub_rn(x2, x1), __fsub_rn(y2, y1));
  g_kp[b][g] = make_float2(kmin, __fmul_rn(kmin, area));
  g_kp3[b][g] = make_float4(kv3, __fmul_rn(kv3, area), area, v3safe);
}

// ---------------- phase 2: FFMA-threshold suspect sweep + masks -------------
// per pair: inter >= kmin*aa + kmin*area  (q-space threshold, 1 FFMA + FSETP)
// grid: x = anchor blocks (782), y = image (8)
__global__ void __launch_bounds__(256) phase2_kernel(const float *__restrict__ anchors,
                                                     const float *__restrict__ gt) {
  const int b = blockIdx.y;
  const int tid = threadIdx.x;
  __shared__ float4 sbox[NG];
  __shared__ float2 skp[NG];
  __shared__ float4 skp3[NG];
  if (tid < NG) {
    const float *gp = gt + (size_t)(b * NG + tid) * 4;
    float cx = gp[0], cy = gp[1], w = gp[2], h = gp[3];
    float tx = __fmul_rn(0.5f, w), ty = __fmul_rn(0.5f, h);
    float x1 = __fsub_rn(cx, tx), x2 = __fadd_rn(cx, tx);
    float y1 = __fsub_rn(cy, ty), y2 = __fadd_rn(cy, ty);
    sbox[tid] = make_float4(x1, y1, x2, y2);
    skp[tid] = g_kp[b][tid];
    skp3[tid] = g_kp3[b][tid];
  }
  __syncthreads();
  int a = blockIdx.x * 256 + tid;
  if (a >= NA) return;  // NA % 32 == 0 -> warp-uniform, ballots safe

  float4 v = reinterpret_cast<const float4 *>(anchors)[(size_t)b * NA + a];
  float tx = __fmul_rn(0.5f, v.z), ty = __fmul_rn(0.5f, v.w);
  float ax1 = __fsub_rn(v.x, tx), ax2 = __fadd_rn(v.x, tx);
  float ay1 = __fsub_rn(v.y, ty), ay2 = __fadd_rn(v.y, ty);
  float aa = __fmul_rn(__fsub_rn(ax2, ax1), __fsub_rn(ay2, ay1));

  unsigned long long mask = 0ull;
#pragma unroll 8
  for (int g = 0; g < NG; g++) {
    float4 gb = sbox[g];
    float2 kp = skp[g];
    float ltx = fmaxf(gb.x, ax1);
    float lty = fmaxf(gb.y, ay1);
    float rbx = fminf(gb.z, ax2);
    float rby = fminf(gb.w, ay2);
    float wx = fmaxf(__fsub_rn(rbx, ltx), 0.0f);
    float wy = fmaxf(__fsub_rn(rby, lty), 0.0f);
    float inter = __fmul_rn(wx, wy);
    if (inter >= __fmaf_rn(kp.x, aa, kp.y)) {  // rare (~0.5%/pair)
      mask |= (1ull << g);
      float4 k3 = skp3[g];
      if (inter >= __fmaf_rn(k3.x, aa, k3.y)) {  // very rare: top-4 band
        float uni = __fsub_rn(__fadd_rn(k3.z, aa), inter);
        float iou_ex = __fdiv_rn(inter, uni);
        if (iou_ex >= k3.w) {
          int slot = atomicAdd(&g_candcnt[b][g], 1);
          if (slot < CAND_MAX)
            g_cand[b][g][slot] =
                ((unsigned long long)__float_as_uint(iou_ex) << 32) |
                (0xFFFFFFFFu - (unsigned int)a);
        }
      }
    }
  }
  bool flag = mask != 0ull;
  unsigned int wm = __ballot_sync(0xFFFFFFFFu, flag);
  if (flag) {
    int lane = tid & 31;
    int leader = __ffs(wm) - 1;
    int base = 0;
    if (lane == leader) base = atomicAdd(&g_flagcnt[b], __popc(wm));
    base = __shfl_sync(wm, base, leader);
    int p = base + __popc(wm & ((1u << lane) - 1u));
    g_flagged[b][p] = a;
    g_fmask[b][p] = mask;
  }
}

// ---------------- phase 2b: exact top-4 (values + indices) ------------------
__global__ void cand_select_kernel() {
  int t = blockIdx.x * blockDim.x + threadIdx.x;
  if (t >= NB * NG) return;
  int b = t >> 6, g = t & 63;
  int cnt = g_candcnt[b][g];
  if (cnt > CAND_MAX) cnt = CAND_MAX;
  unsigned long long best[4] = {0ull, 0ull, 0ull, 0ull};
  for (int i = 0; i < cnt; i++) {
    unsigned long long key = g_cand[b][g][i];
    if (key > best[3]) insert4(best, key);
  }
#pragma unroll
  for (int k = 0; k < 4; k++) {
    g_topval[b][g][k] = __uint_as_float((unsigned int)(best[k] >> 32));
    g_topidx[b][g][k] = (int)(0xFFFFFFFFu - (unsigned int)best[k]);
  }
}

// ---------------- phase 2c: exact positives over suspect PAIRS only ---------
// grid: (POSB, NB). Per flagged anchor, only its masked GT bits (~1-2) are
// re-evaluated with exact __fdiv_rn: threshold (>=0.7f) and eq (== hq).
__global__ void __launch_bounds__(256) posdetect_kernel(const float *__restrict__ anchors,
                                                        const float *__restrict__ gt,
                                                        SplitKeys sk) {
  const int b = blockIdx.y;
  const int tid = threadIdx.x;
  __shared__ float4 sbox[NG];
  __shared__ float2 sah[NG];  // (area, hq exact)
  if (tid < NG) {
    const float *gp = gt + (size_t)(b * NG + tid) * 4;
    float cx = gp[0], cy = gp[1], w = gp[2], h = gp[3];
    float tx = __fmul_rn(0.5f, w), ty = __fmul_rn(0.5f, h);
    float x1 = __fsub_rn(cx, tx), x2 = __fadd_rn(cx, tx);
    float y1 = __fsub_rn(cy, ty), y2 = __fadd_rn(cy, ty);
    sbox[tid] = make_float4(x1, y1, x2, y2);
    sah[tid] = make_float2(__fmul_rn(__fsub_rn(x2, x1), __fsub_rn(y2, y1)),
                           g_topval[b][tid][0]);
  }
  __syncthreads();

  const int n = g_flagcnt[b];
  const int step = POSB * 256;
  const int rounds = (n + step - 1) / step;  // uniform across block
  for (int r = 0; r < rounds; r++) {
    int i = blockIdx.x * 256 + tid + r * step;
    bool active = i < n;
    bool pos = false;
    int a = 0;
    if (active) {
      a = g_flagged[b][i];
      unsigned long long mask = g_fmask[b][i];
      float4 v = reinterpret_cast<const float4 *>(anchors)[(size_t)b * NA + a];
      float tx = __fmul_rn(0.5f, v.z), ty = __fmul_rn(0.5f, v.w);
      float ax1 = __fsub_rn(v.x, tx), ax2 = __fadd_rn(v.x, tx);
      float ay1 = __fsub_rn(v.y, ty), ay2 = __fadd_rn(v.y, ty);
      float aa = __fmul_rn(__fsub_rn(ax2, ax1), __fsub_rn(ay2, ay1));
      while (mask) {
        int g = __ffsll((long long)mask) - 1;
        mask &= mask - 1;
        float4 gb = sbox[g];
        float2 ah = sah[g];
        float ltx = fmaxf(gb.x, ax1);
        float lty = fmaxf(gb.y, ay1);
        float rbx = fminf(gb.z, ax2);
        float rby = fminf(gb.w, ay2);
        float wx = fmaxf(__fsub_rn(rbx, ltx), 0.0f);
        float wy = fmaxf(__fsub_rn(rby, lty), 0.0f);
        float inter = __fmul_rn(wx, wy);
        float uni = __fsub_rn(__fadd_rn(ah.x, aa), inter);
        float iou = __fdiv_rn(inter, uni);
        pos |= (iou >= 0.7f) || (iou == ah.y);
      }
    }
    unsigned int wm = __ballot_sync(0xFFFFFFFFu, active && pos);
    if (active && pos) {
      unsigned int o0, o1;
      threefry2x32(sk.k[2 * b], sk.k[2 * b + 1], 0u, (unsigned int)a, o0, o1);
      unsigned int u = o0 ^ o1;
      float f = __uint_as_float((u >> 9) | 0x3f800000u);
      unsigned int rb = __float_as_uint(__fsub_rn(f, 1.0f));  // exact: f in [1,2)
      unsigned long long key = ((unsigned long long)rb << 32) | (unsigned int)a;
      int lane = tid & 31;
      int leader = __ffs(wm) - 1;
      int base = 0;
      if (lane == leader) base = atomicAdd(&g_npos[b], __popc(wm));
      base = __shfl_sync(wm, base, leader);
      g_poskeys[b][base + __popc(wm & ((1u << lane) - 1u))] = key;
    }
  }
}

// ---------------- phase 3: select 128 smallest keys -> g_sel ----------------
__global__ void __launch_bounds__(1024) phase3_kernel() {
  const int b = blockIdx.x;
  const int tid = threadIdx.x;
  const int n = g_npos[b];
  __shared__ int hist[256];
  __shared__ unsigned long long s_prefix;
  __shared__ int s_want;
  __shared__ int s_nsel;

  unsigned long long thresh;
  if (n <= MAXPOS) {
    thresh = ~0ull;  // select all positives
  } else {
    if (tid == 0) { s_prefix = 0ull; s_want = MAXPOS; }
    __syncthreads();
    for (int shift = 56; shift >= 0; shift -= 8) {
      if (tid < 256) hist[tid] = 0;
      __syncthreads();
      unsigned long long pref = s_prefix;
      for (int i = tid; i < n; i += 1024) {
        unsigned long long k = g_poskeys[b][i];
        bool match = (shift == 56) ? true
                                   : ((k >> (shift + 8)) == (pref >> (shift + 8)));
        if (match) atomicAdd(&hist[(int)((k >> shift) & 255u)], 1);
      }
      __syncthreads();
      if (tid == 0) {
        int want = s_want;
        int d = 0;
        for (; d < 256; d++) {
          if (want <= hist[d]) break;
          want -= hist[d];
        }
        s_prefix = pref | ((unsigned long long)d << shift);
        s_want = want;
      }
      __syncthreads();
    }
    thresh = s_prefix;  // exact 128th-smallest key (keys unique by anchor id)
  }

  if (tid == 0) s_nsel = 0;
  __syncthreads();
  for (int i = tid; i < n; i += 1024) {
    unsigned long long k = g_poskeys[b][i];
    if (k <= thresh) {
      int slot = atomicAdd(&s_nsel, 1);
      g_sel[b][slot] = (unsigned int)(k & 0xFFFFFFFFull);
    }
  }
  __syncthreads();
  if (tid == 0) g_nsel[b] = s_nsel;
}

// ---------------- phase 3b: exact argmax for selected anchors -> counts -----
__global__ void argmax_count_kernel(const float *__restrict__ anchors,
                                    const float *__restrict__ gt) {
  const int b = blockIdx.x;
  const int tid = threadIdx.x;  // 128 threads
  __shared__ float4 sbox[NG];
  __shared__ float sarea[NG];
  __shared__ int scnt[NG];
  if (tid < NG) {
    const float *gp = gt + (size_t)(b * NG + tid) * 4;
    float cx = gp[0], cy = gp[1], w = gp[2], h = gp[3];
    float tx = __fmul_rn(0.5f, w), ty = __fmul_rn(0.5f, h);
    float x1 = __fsub_rn(cx, tx), x2 = __fadd_rn(cx, tx);
    float y1 = __fsub_rn(cy, ty), y2 = __fadd_rn(cy, ty);
    sbox[tid] = make_float4(x1, y1, x2, y2);
    sarea[tid] = __fmul_rn(__fsub_rn(x2, x1), __fsub_rn(y2, y1));
    scnt[tid] = 0;
  }
  __syncthreads();
  if (tid < g_nsel[b]) {
    int a = (int)g_sel[b][tid];
    float4 v = reinterpret_cast<const float4 *>(anchors)[(size_t)b * NA + a];
    float tx = __fmul_rn(0.5f, v.z), ty = __fmul_rn(0.5f, v.w);
    float ax1 = __fsub_rn(v.x, tx), ax2 = __fadd_rn(v.x, tx);
    float ay1 = __fsub_rn(v.y, ty), ay2 = __fadd_rn(v.y, ty);
    float aa = __fmul_rn(__fsub_rn(ax2, ax1), __fsub_rn(ay2, ay1));
    float best = -1.0f;
    int bg = 0;
    for (int g = 0; g < NG; g++) {
      float4 gb = sbox[g];
      float ltx = fmaxf(gb.x, ax1);
      float lty = fmaxf(gb.y, ay1);
      float rbx = fminf(gb.z, ax2);
      float rby = fminf(gb.w, ay2);
      float wx = fmaxf(__fsub_rn(rbx, ltx), 0.0f);
      float wy = fmaxf(__fsub_rn(rby, lty), 0.0f);
      float inter = __fmul_rn(wx, wy);
      if (inter == 0.0f) continue;  // iou 0 never beats a positive's best (>0)
      float uni = __fsub_rn(__fadd_rn(sarea[g], aa), inter);
      float iou = __fdiv_rn(inter, uni);
      if (iou > best) { best = iou; bg = g; }  // first-max == jnp.argmax
    }
    atomicAdd(&scnt[bg], 1);
  }
  __syncthreads();
  if (tid < NG) g_counts[b][tid] = scnt[tid];
}

// ---------------- phase 4: emit [pr | gt | valid | scores] as float32 -------
__global__ void write_out_kernel(float *__restrict__ out) {
  int t = blockIdx.x * blockDim.x + threadIdx.x;
  if (t >= NB * NG * NK) return;
  int b = t >> 8;
  int g = (t >> 2) & 63;
  int k = t & 3;
  int c = g_counts[b][g];
  if (c > NK) c = NK;
  bool valid = k < c;
  float val = g_topval[b][g][k];
  int idx = g_topidx[b][g][k];
  const int SEC = NB * NG * NK;  // 2048
  int o = b * (NG * NK) + g * NK + k;
  out[o]           = valid ? (float)idx : -1.0f;
  out[SEC + o]     = valid ? (float)g : -1.0f;
  out[2 * SEC + o] = valid ? 1.0f : 0.0f;
  out[3 * SEC + o] = valid ? val : 0.0f;
}

// ---------------- launch -----------------------------------------------------
extern "C" void kernel_launch(void *const *d_in, const int *in_sizes, int n_in,
                              void *d_out, int out_size) {
  const float *anchors = (const float *)d_in[0];   // [8, 200000, 4] cxcywh
  const float *gt      = (const float *)d_in[1];   // [8, 64, 4] cxcywh

  // JAX partitionable split (foldlike): key_b = threefry((0,42), (0,b)), both words
  SplitKeys sk;
  for (int b = 0; b < NB; b++) {
    unsigned int o0, o1;
    threefry2x32(0u, 42u, 0u, (unsigned int)b, o0, o1);
    sk.k[2 * b] = o0;
    sk.k[2 * b + 1] = o1;
  }

  init_kernel<<<2, 256>>>();
  phase1_kernel<<<dim3(NCHUNK, NG / GQ, NB), 256>>>(anchors, gt);
  merge_parts_kernel<<<2, 256>>>(gt);
  phase2_kernel<<<dim3((NA + 255) / 256, NB), 256>>>(anchors, gt);
  cand_select_kernel<<<2, 256>>>();
  posdetect_kernel<<<dim3(POSB, NB), 256>>>(anchors, gt, sk);
  phase3_kernel<<<NB, 1024>>>();
  argmax_count_kernel<<<NB, 128>>>(anchors, gt);
  write_out_kernel<<<NB, 256>>>((float *)d_out);
}

// round 16
// speedup vs baseline: 3.7521x; 1.3908x over previous
#include <cuda_runtime.h>
#include <stdint.h>

#define NB 8
#define NA 200000
#define NG 64
#define NK 4
#define NSUB 25000           // phase1 subsample (first 1/8 of anchors)
#define NCHUNK1 4
#define CHUNK1 6250
#define GQ 8
#define MAXPOS 128
#define CAND_MAX 1024
#define POSB 32
#define KTHR 0.41174f        // q-space 0.7 threshold minus margin (0.7/1.7 = 0.4117647)

// ---------------- scratch (static __device__, no allocation) ----------------
__device__ float g_partq[NB * NG * NCHUNK1 * 4];  // chunk-partial 4-slot q maxima
__device__ float2 g_kp[NB][NG];                   // (kmin, kmin*area) primary threshold
__device__ float4 g_kp3[NB][NG];                  // (kv3, kv3*area, area, v3safe)
__device__ float g_topval[NB][NG][NK];            // EXACT top4 values
__device__ int   g_topidx[NB][NG][NK];            // EXACT top4 indices
__device__ unsigned long long g_cand[NB][NG][CAND_MAX];
__device__ int g_candcnt[NB][NG];
__device__ int g_flagged[NB][NA];                 // suspect anchors (compact)
__device__ unsigned long long g_fmask[NB][NA];    // per-suspect GT bitmask
__device__ int g_flagcnt[NB];
__device__ unsigned long long g_poskeys[NB][NA];
__device__ int g_npos[NB];
__device__ unsigned int g_sel[NB][MAXPOS];        // selected anchor ids
__device__ int g_nsel[NB];

struct SplitKeys { unsigned int k[2 * NB]; };

// ---------------- threefry2x32 (exact JAX kernel: 20 rounds) ----------------
__host__ __device__ inline void threefry2x32(unsigned int k0, unsigned int k1,
                                             unsigned int c0, unsigned int c1,
                                             unsigned int &o0, unsigned int &o1) {
  unsigned int ks2 = 0x1BD11BDAu ^ k0 ^ k1;
  unsigned int x0 = c0 + k0, x1 = c1 + k1;
#define TFR(r) do { x0 += x1; x1 = (x1 << (r)) | (x1 >> (32 - (r))); x1 ^= x0; } while (0)
  TFR(13); TFR(15); TFR(26); TFR(6);
  x0 += k1;  x1 += ks2 + 1u;
  TFR(17); TFR(29); TFR(16); TFR(24);
  x0 += ks2; x1 += k0 + 2u;
  TFR(13); TFR(15); TFR(26); TFR(6);
  x0 += k0;  x1 += k1 + 3u;
  TFR(17); TFR(29); TFR(16); TFR(24);
  x0 += k1;  x1 += ks2 + 4u;
  TFR(13); TFR(15); TFR(26); TFR(6);
  x0 += ks2; x1 += k0 + 5u;
#undef TFR
  o0 = x0; o1 = x1;
}

// insert u64 key into descending sorted 4-list; caller guarantees key > t[3]
__device__ __forceinline__ void insert4(unsigned long long *t, unsigned long long key) {
  if (key > t[1]) {
    t[3] = t[2]; t[2] = t[1];
    if (key > t[0]) { t[1] = t[0]; t[0] = key; } else { t[1] = key; }
  } else {
    if (key > t[2]) { t[3] = t[2]; t[2] = key; } else { t[3] = key; }
  }
}

// ---------------- phase 1: 4-slot q maxima over a SUBSAMPLE (GT-major) ------
// 4th-best over a subset <= 4th-best over the full set, so min(4 disjoint slot
// maxima over the subsample) is a valid (loose) lower bound on v3 in q-space.
// Block (0,0,0) also zeroes all global counters (consumers are later kernels).
// grid: x = chunk (4), y = gt group (8 groups of 8), z = image (8)
__global__ void __launch_bounds__(256) phase1_kernel(const float *__restrict__ anchors,
                                                     const float *__restrict__ gt) {
  const int b = blockIdx.z;
  const int g0 = blockIdx.y * GQ;
  const int ch = blockIdx.x;
  const int tid = threadIdx.x;

  if (blockIdx.x == 0 && blockIdx.y == 0 && blockIdx.z == 0) {
    if (tid < NB) { g_npos[tid] = 0; g_flagcnt[tid] = 0; g_nsel[tid] = 0; }
    ((int *)g_candcnt)[tid] = 0;
    ((int *)g_candcnt)[tid + 256] = 0;
  }

  __shared__ float sg[GQ][5];
  if (tid < GQ) {
    const float *gp = gt + (size_t)(b * NG + g0 + tid) * 4;
    float cx = gp[0], cy = gp[1], w = gp[2], h = gp[3];
    float tx = __fmul_rn(0.5f, w), ty = __fmul_rn(0.5f, h);
    float x1 = __fsub_rn(cx, tx), x2 = __fadd_rn(cx, tx);
    float y1 = __fsub_rn(cy, ty), y2 = __fadd_rn(cy, ty);
    sg[tid][0] = x1; sg[tid][1] = y1; sg[tid][2] = x2; sg[tid][3] = y2;
    sg[tid][4] = __fmul_rn(__fsub_rn(x2, x1), __fsub_rn(y2, y1));
  }
  __syncthreads();

  float gx1[GQ], gy1[GQ], gx2[GQ], gy2[GQ], ga[GQ];
#pragma unroll
  for (int j = 0; j < GQ; j++) {
    gx1[j] = sg[j][0]; gy1[j] = sg[j][1]; gx2[j] = sg[j][2]; gy2[j] = sg[j][3]; ga[j] = sg[j][4];
  }

  float m[GQ][4];
#pragma unroll
  for (int j = 0; j < GQ; j++)
#pragma unroll
    for (int s = 0; s < 4; s++) m[j][s] = 0.0f;

  const int a0 = ch * CHUNK1;
  const int aend = a0 + CHUNK1;
  const float4 *ap = reinterpret_cast<const float4 *>(anchors) + (size_t)b * NA;

  int a = a0 + tid;
  for (; a + 768 < aend; a += 1024) {
#pragma unroll
    for (int s = 0; s < 4; s++) {
      float4 v = ap[a + s * 256];
      float tx = __fmul_rn(0.5f, v.z), ty = __fmul_rn(0.5f, v.w);
      float ax1 = __fsub_rn(v.x, tx), ax2 = __fadd_rn(v.x, tx);
      float ay1 = __fsub_rn(v.y, ty), ay2 = __fadd_rn(v.y, ty);
      float aa = __fmul_rn(__fsub_rn(ax2, ax1), __fsub_rn(ay2, ay1));
#pragma unroll
      for (int j = 0; j < GQ; j++) {
        float ltx = fmaxf(gx1[j], ax1);
        float lty = fmaxf(gy1[j], ay1);
        float rbx = fminf(gx2[j], ax2);
        float rby = fminf(gy2[j], ay2);
        float wx = fmaxf(__fsub_rn(rbx, ltx), 0.0f);
        float wy = fmaxf(__fsub_rn(rby, lty), 0.0f);
        float inter = __fmul_rn(wx, wy);
        float ssum = __fadd_rn(ga[j], aa);
        float q = __fdividef(inter, ssum);  // approx; 0 when inter==0
        m[j][s] = fmaxf(m[j][s], q);
      }
    }
  }
  for (; a < aend; a += 256) {  // tail -> slot 0 (slots stay disjoint)
    float4 v = ap[a];
    float tx = __fmul_rn(0.5f, v.z), ty = __fmul_rn(0.5f, v.w);
    float ax1 = __fsub_rn(v.x, tx), ax2 = __fadd_rn(v.x, tx);
    float ay1 = __fsub_rn(v.y, ty), ay2 = __fadd_rn(v.y, ty);
    float aa = __fmul_rn(__fsub_rn(ax2, ax1), __fsub_rn(ay2, ay1));
#pragma unroll
    for (int j = 0; j < GQ; j++) {
      float ltx = fmaxf(gx1[j], ax1);
      float lty = fmaxf(gy1[j], ay1);
      float rbx = fminf(gx2[j], ax2);
      float rby = fminf(gy2[j], ay2);
      float wx = fmaxf(__fsub_rn(rbx, ltx), 0.0f);
      float wy = fmaxf(__fsub_rn(rby, lty), 0.0f);
      float inter = __fmul_rn(wx, wy);
      float ssum = __fadd_rn(ga[j], aa);
      float q = __fdividef(inter, ssum);
      m[j][0] = fmaxf(m[j][0], q);
    }
  }

  // block max-reduction of all 32 accumulators (stride 33 -> conflict-free)
  __shared__ float red[256 * 33];
#pragma unroll
  for (int j = 0; j < GQ; j++)
#pragma unroll
    for (int s = 0; s < 4; s++) red[tid * 33 + j * 4 + s] = m[j][s];
  __syncthreads();
  for (int st = 128; st > 0; st >>= 1) {
    if (tid < st) {
#pragma unroll
      for (int k = 0; k < 32; k++)
        red[tid * 33 + k] = fmaxf(red[tid * 33 + k], red[(tid + st) * 33 + k]);
    }
    __syncthreads();
  }
  if (tid < 32) {
    int j = tid >> 2, s = tid & 3;
    g_partq[(size_t)((b * NG + g0 + j) * NCHUNK1 + ch) * 4 + s] = red[j * 4 + s];
  }
}

// ---------------- phase 1b: merge -> q thresholds + iou-space v3safe --------
__global__ void merge_parts_kernel(const float *__restrict__ gt) {
  int t = blockIdx.x * blockDim.x + threadIdx.x;
  if (t >= NB * NG) return;
  float sm[4] = {0.0f, 0.0f, 0.0f, 0.0f};
  for (int c = 0; c < NCHUNK1; c++) {
    const float *p = &g_partq[(size_t)(t * NCHUNK1 + c) * 4];
#pragma unroll
    for (int s = 0; s < 4; s++) sm[s] = fmaxf(sm[s], p[s]);
  }
  float thr_q = fminf(fminf(sm[0], sm[1]), fminf(sm[2], sm[3]));  // <= q(v3)+eps
  int b = t >> 6, g = t & 63;
  float kv3 = fmaxf(__fmul_rn(thr_q, 1.0f - 1e-5f), 1e-30f);
  float thr_iou = __fdividef(thr_q, __fsub_rn(1.0f, thr_q));  // q <= 0.5 -> safe
  float v3safe = fmaxf(__fmul_rn(thr_iou, 1.0f - 1e-5f), 1e-35f);
  float kmin = fminf(kv3, KTHR);

  const float *gp = gt + (size_t)(b * NG + g) * 4;
  float w = gp[2], h = gp[3];
  float tx = __fmul_rn(0.5f, w), ty = __fmul_rn(0.5f, h);
  float x1 = __fsub_rn(gp[0], tx), x2 = __fadd_rn(gp[0], tx);
  float y1 = __fsub_rn(gp[1], ty), y2 = __fadd_rn(gp[1], ty);
  float area = __fmul_rn(__fsub_rn(x2, x1), __fsub_rn(y2, y1));
  g_kp[b][g] = make_float2(kmin, __fmul_rn(kmin, area));
  g_kp3[b][g] = make_float4(kv3, __fmul_rn(kv3, area), area, v3safe);
}

// ---------------- phase 2: clamp-free FFMA-threshold suspect sweep ----------
// prod = (rbx-ltx)*(rby-lty); suspect iff prod >= thr && (rbx-ltx) > 0.
// thr > 0, so both-negative fake positives are excluded by the sign check;
// in the pass region prod is bit-identical to the reference clamped inter.
// grid: x = anchor blocks (782), y = image (8)
__global__ void __launch_bounds__(256) phase2_kernel(const float *__restrict__ anchors,
                                                     const float *__restrict__ gt) {
  const int b = blockIdx.y;
  const int tid = threadIdx.x;
  __shared__ float4 sbox[NG];
  __shared__ float2 skp[NG];
  __shared__ float4 skp3[NG];
  if (tid < NG) {
    const float *gp = gt + (size_t)(b * NG + tid) * 4;
    float cx = gp[0], cy = gp[1], w = gp[2], h = gp[3];
    float tx = __fmul_rn(0.5f, w), ty = __fmul_rn(0.5f, h);
    float x1 = __fsub_rn(cx, tx), x2 = __fadd_rn(cx, tx);
    float y1 = __fsub_rn(cy, ty), y2 = __fadd_rn(cy, ty);
    sbox[tid] = make_float4(x1, y1, x2, y2);
    skp[tid] = g_kp[b][tid];
    skp3[tid] = g_kp3[b][tid];
  }
  __syncthreads();
  int a = blockIdx.x * 256 + tid;
  if (a >= NA) return;  // NA % 32 == 0 -> warp-uniform, ballots safe

  float4 v = reinterpret_cast<const float4 *>(anchors)[(size_t)b * NA + a];
  float tx = __fmul_rn(0.5f, v.z), ty = __fmul_rn(0.5f, v.w);
  float ax1 = __fsub_rn(v.x, tx), ax2 = __fadd_rn(v.x, tx);
  float ay1 = __fsub_rn(v.y, ty), ay2 = __fadd_rn(v.y, ty);
  float aa = __fmul_rn(__fsub_rn(ax2, ax1), __fsub_rn(ay2, ay1));

  unsigned long long mask = 0ull;
#pragma unroll 8
  for (int g = 0; g < NG; g++) {
    float4 gb = sbox[g];
    float2 kp = skp[g];
    float ltx = fmaxf(gb.x, ax1);
    float lty = fmaxf(gb.y, ay1);
    float rbx = fminf(gb.z, ax2);
    float rby = fminf(gb.w, ay2);
    float wxr = __fsub_rn(rbx, ltx);
    float wyr = __fsub_rn(rby, lty);
    float prod = __fmul_rn(wxr, wyr);
    if (prod >= __fmaf_rn(kp.x, aa, kp.y) && wxr > 0.0f) {  // rare (~1%/pair)
      mask |= (1ull << g);
      float4 k3 = skp3[g];
      if (prod >= __fmaf_rn(k3.x, aa, k3.y)) {  // top-4 band (prod == inter here)
        float uni = __fsub_rn(__fadd_rn(k3.z, aa), prod);
        float iou_ex = __fdiv_rn(prod, uni);
        if (iou_ex >= k3.w) {
          int slot = atomicAdd(&g_candcnt[b][g], 1);
          if (slot < CAND_MAX)
            g_cand[b][g][slot] =
                ((unsigned long long)__float_as_uint(iou_ex) << 32) |
                (0xFFFFFFFFu - (unsigned int)a);
        }
      }
    }
  }
  bool flag = mask != 0ull;
  unsigned int wm = __ballot_sync(0xFFFFFFFFu, flag);
  if (flag) {
    int lane = tid & 31;
    int leader = __ffs(wm) - 1;
    int base = 0;
    if (lane == leader) base = atomicAdd(&g_flagcnt[b], __popc(wm));
    base = __shfl_sync(wm, base, leader);
    int p = base + __popc(wm & ((1u << lane) - 1u));
    g_flagged[b][p] = a;
    g_fmask[b][p] = mask;
  }
}

// ---------------- phase 2b: exact top-4 (values + indices) ------------------
__global__ void cand_select_kernel() {
  int t = blockIdx.x * blockDim.x + threadIdx.x;
  if (t >= NB * NG) return;
  int b = t >> 6, g = t & 63;
  int cnt = g_candcnt[b][g];
  if (cnt > CAND_MAX) cnt = CAND_MAX;
  unsigned long long best[4] = {0ull, 0ull, 0ull, 0ull};
  for (int i = 0; i < cnt; i++) {
    unsigned long long key = g_cand[b][g][i];
    if (key > best[3]) insert4(best, key);
  }
#pragma unroll
  for (int k = 0; k < 4; k++) {
    g_topval[b][g][k] = __uint_as_float((unsigned int)(best[k] >> 32));
    g_topidx[b][g][k] = (int)(0xFFFFFFFFu - (unsigned int)best[k]);
  }
}

// ---------------- phase 2c: exact positives over suspect PAIRS only ---------
// grid: (POSB, NB). Per flagged anchor, only its masked GT bits are
// re-evaluated with exact __fdiv_rn: threshold (>=0.7f) and eq (== hq).
__global__ void __launch_bounds__(256) posdetect_kernel(const float *__restrict__ anchors,
                                                        const float *__restrict__ gt,
                                                        SplitKeys sk) {
  const int b = blockIdx.y;
  const int tid = threadIdx.x;
  __shared__ float4 sbox[NG];
  __shared__ float2 sah[NG];  // (area, hq exact)
  if (tid < NG) {
    const float *gp = gt + (size_t)(b * NG + tid) * 4;
    float cx = gp[0], cy = gp[1], w = gp[2], h = gp[3];
    float tx = __fmul_rn(0.5f, w), ty = __fmul_rn(0.5f, h);
    float x1 = __fsub_rn(cx, tx), x2 = __fadd_rn(cx, tx);
    float y1 = __fsub_rn(cy, ty), y2 = __fadd_rn(cy, ty);
    sbox[tid] = make_float4(x1, y1, x2, y2);
    sah[tid] = make_float2(__fmul_rn(__fsub_rn(x2, x1), __fsub_rn(y2, y1)),
                           g_topval[b][tid][0]);
  }
  __syncthreads();

  const int n = g_flagcnt[b];
  const int step = POSB * 256;
  const int rounds = (n + step - 1) / step;  // uniform across block
  for (int r = 0; r < rounds; r++) {
    int i = blockIdx.x * 256 + tid + r * step;
    bool active = i < n;
    bool pos = false;
    int a = 0;
    if (active) {
      a = g_flagged[b][i];
      unsigned long long mask = g_fmask[b][i];
      float4 v = reinterpret_cast<const float4 *>(anchors)[(size_t)b * NA + a];
      float tx = __fmul_rn(0.5f, v.z), ty = __fmul_rn(0.5f, v.w);
      float ax1 = __fsub_rn(v.x, tx), ax2 = __fadd_rn(v.x, tx);
      float ay1 = __fsub_rn(v.y, ty), ay2 = __fadd_rn(v.y, ty);
      float aa = __fmul_rn(__fsub_rn(ax2, ax1), __fsub_rn(ay2, ay1));
      while (mask) {
        int g = __ffsll((long long)mask) - 1;
        mask &= mask - 1;
        float4 gb = sbox[g];
        float2 ah = sah[g];
        float ltx = fmaxf(gb.x, ax1);
        float lty = fmaxf(gb.y, ay1);
        float rbx = fminf(gb.z, ax2);
        float rby = fminf(gb.w, ay2);
        float wx = fmaxf(__fsub_rn(rbx, ltx), 0.0f);
        float wy = fmaxf(__fsub_rn(rby, lty), 0.0f);
        float inter = __fmul_rn(wx, wy);
        float uni = __fsub_rn(__fadd_rn(ah.x, aa), inter);
        float iou = __fdiv_rn(inter, uni);
        pos |= (iou >= 0.7f) || (iou == ah.y);
      }
    }
    unsigned int wm = __ballot_sync(0xFFFFFFFFu, active && pos);
    if (active && pos) {
      unsigned int o0, o1;
      threefry2x32(sk.k[2 * b], sk.k[2 * b + 1], 0u, (unsigned int)a, o0, o1);
      unsigned int u = o0 ^ o1;
      float f = __uint_as_float((u >> 9) | 0x3f800000u);
      unsigned int rb = __float_as_uint(__fsub_rn(f, 1.0f));  // exact: f in [1,2)
      unsigned long long key = ((unsigned long long)rb << 32) | (unsigned int)a;
      int lane = tid & 31;
      int leader = __ffs(wm) - 1;
      int base = 0;
      if (lane == leader) base = atomicAdd(&g_npos[b], __popc(wm));
      base = __shfl_sync(wm, base, leader);
      g_poskeys[b][base + __popc(wm & ((1u << lane) - 1u))] = key;
    }
  }
}

// ---------------- phase 3: select 128 smallest keys -> g_sel ----------------
__global__ void __launch_bounds__(1024) phase3_kernel() {
  const int b = blockIdx.x;
  const int tid = threadIdx.x;
  const int n = g_npos[b];
  __shared__ int hist[256];
  __shared__ unsigned long long s_prefix;
  __shared__ int s_want;
  __shared__ int s_nsel;

  unsigned long long thresh;
  if (n <= MAXPOS) {
    thresh = ~0ull;  // select all positives
  } else {
    if (tid == 0) { s_prefix = 0ull; s_want = MAXPOS; }
    __syncthreads();
    for (int shift = 56; shift >= 0; shift -= 8) {
      if (tid < 256) hist[tid] = 0;
      __syncthreads();
      unsigned long long pref = s_prefix;
      for (int i = tid; i < n; i += 1024) {
        unsigned long long k = g_poskeys[b][i];
        bool match = (shift == 56) ? true
                                   : ((k >> (shift + 8)) == (pref >> (shift + 8)));
        if (match) atomicAdd(&hist[(int)((k >> shift) & 255u)], 1);
      }
      __syncthreads();
      if (tid == 0) {
        int want = s_want;
        int d = 0;
        for (; d < 256; d++) {
          if (want <= hist[d]) break;
          want -= hist[d];
        }
        s_prefix = pref | ((unsigned long long)d << shift);
        s_want = want;
      }
      __syncthreads();
    }
    thresh = s_prefix;  // exact 128th-smallest key (keys unique by anchor id)
  }

  if (tid == 0) s_nsel = 0;
  __syncthreads();
  for (int i = tid; i < n; i += 1024) {
    unsigned long long k = g_poskeys[b][i];
    if (k <= thresh) {
      int slot = atomicAdd(&s_nsel, 1);
      g_sel[b][slot] = (unsigned int)(k & 0xFFFFFFFFull);
    }
  }
  __syncthreads();
  if (tid == 0) g_nsel[b] = s_nsel;
}

// ---------------- finalize: exact argmax for selected + emit output ---------
// grid: NB blocks, 256 threads. Output [pr | gt | valid | scores], float32.
__global__ void finalize_kernel(const float *__restrict__ anchors,
                                const float *__restrict__ gt,
                                float *__restrict__ out) {
  const int b = blockIdx.x;
  const int tid = threadIdx.x;
  __shared__ float4 sbox[NG];
  __shared__ float sarea[NG];
  __shared__ int scnt[NG];
  if (tid < NG) {
    const float *gp = gt + (size_t)(b * NG + tid) * 4;
    float cx = gp[0], cy = gp[1], w = gp[2], h = gp[3];
    float tx = __fmul_rn(0.5f, w), ty = __fmul_rn(0.5f, h);
    float x1 = __fsub_rn(cx, tx), x2 = __fadd_rn(cx, tx);
    float y1 = __fsub_rn(cy, ty), y2 = __fadd_rn(cy, ty);
    sbox[tid] = make_float4(x1, y1, x2, y2);
    sarea[tid] = __fmul_rn(__fsub_rn(x2, x1), __fsub_rn(y2, y1));
    scnt[tid] = 0;
  }
  __syncthreads();
  if (tid < g_nsel[b]) {  // exact argmax (matches) for selected positives only
    int a = (int)g_sel[b][tid];
    float4 v = reinterpret_cast<const float4 *>(anchors)[(size_t)b * NA + a];
    float tx = __fmul_rn(0.5f, v.z), ty = __fmul_rn(0.5f, v.w);
    float ax1 = __fsub_rn(v.x, tx), ax2 = __fadd_rn(v.x, tx);
    float ay1 = __fsub_rn(v.y, ty), ay2 = __fadd_rn(v.y, ty);
    float aa = __fmul_rn(__fsub_rn(ax2, ax1), __fsub_rn(ay2, ay1));
    float best = -1.0f;
    int bg = 0;
    for (int g = 0; g < NG; g++) {
      float4 gb = sbox[g];
      float ltx = fmaxf(gb.x, ax1);
      float lty = fmaxf(gb.y, ay1);
      float rbx = fminf(gb.z, ax2);
      float rby = fminf(gb.w, ay2);
      float wx = fmaxf(__fsub_rn(rbx, ltx), 0.0f);
      float wy = fmaxf(__fsub_rn(rby, lty), 0.0f);
      float inter = __fmul_rn(wx, wy);
      if (inter == 0.0f) continue;  // iou 0 never beats a positive's best (>0)
      float uni = __fsub_rn(__fadd_rn(sarea[g], aa), inter);
      float iou = __fdiv_rn(inter, uni);
      if (iou > best) { best = iou; bg = g; }  // first-max == jnp.argmax
    }
    atomicAdd(&scnt[bg], 1);
  }
  __syncthreads();
  {  // 256 threads emit this image's 256 (g,k) slots in all 4 sections
    int g = tid >> 2, k = tid & 3;
    int c = scnt[g];
    if (c > NK) c = NK;
    bool valid = k < c;
    float val = g_topval[b][g][k];
    int idx = g_topidx[b][g][k];
    const int SEC = NB * NG * NK;  // 2048
    int o = b * (NG * NK) + tid;
    out[o]           = valid ? (float)idx : -1.0f;
    out[SEC + o]     = valid ? (float)g : -1.0f;
    out[2 * SEC + o] = valid ? 1.0f : 0.0f;
    out[3 * SEC + o] = valid ? val : 0.0f;
  }
}

// ---------------- launch -----------------------------------------------------
extern "C" void kernel_launch(void *const *d_in, const int *in_sizes, int n_in,
                              void *d_out, int out_size) {
  const float *anchors = (const float *)d_in[0];   // [8, 200000, 4] cxcywh
  const float *gt      = (const float *)d_in[1];   // [8, 64, 4] cxcywh

  // JAX partitionable split (foldlike): key_b = threefry((0,42), (0,b)), both words
  SplitKeys sk;
  for (int b = 0; b < NB; b++) {
    unsigned int o0, o1;
    threefry2x32(0u, 42u, 0u, (unsigned int)b, o0, o1);
    sk.k[2 * b] = o0;
    sk.k[2 * b + 1] = o1;
  }

  phase1_kernel<<<dim3(NCHUNK1, NG / GQ, NB), 256>>>(anchors, gt);
  merge_parts_kernel<<<2, 256>>>(gt);
  phase2_kernel<<<dim3((NA + 255) / 256, NB), 256>>>(anchors, gt);
  cand_select_kernel<<<2, 256>>>();
  posdetect_kernel<<<dim3(POSB, NB), 256>>>(anchors, gt, sk);
  phase3_kernel<<<NB, 1024>>>();
  finalize_kernel<<<NB, 256>>>(anchors, gt, (float *)d_out);
}